// round 1
// baseline (speedup 1.0000x reference)
#include <cuda_runtime.h>
#include <math.h>

// Problem constants (fixed shapes for this problem)
#define NMAX 50000
#define EMAX 800000
#define TOT_E (EMAX + NMAX)

// ---------------- scratch (static __device__, no allocs) ----------------
__device__ float g_xp[NMAX * 256];      // layer-1 projected features
__device__ float g_h[NMAX * 256];       // layer-1 output (relu)
__device__ float g_asrc[NMAX * 8];      // alpha_src per node/head (layer 1)
__device__ float g_adst[NMAX * 8];      // alpha_dst per node/head (layer 1)
__device__ int   g_deg[NMAX];
__device__ int   g_rowstart[NMAX + 1];
__device__ int   g_cursor[NMAX];
__device__ int   g_csr[TOT_E];          // incoming-edge source lists (CSR by dst)
__device__ float g_hp[NMAX * 2];        // layer-2 projected features
__device__ float g_as2[NMAX];
__device__ float g_ad2[NMAX];
__device__ int   g_is64;                // edge_index dtype flag

// ---------------- edge-index dtype detection (device side) ----------------
__global__ void k_detect(const int* __restrict__ ei32) {
    if (blockIdx.x == 0 && threadIdx.x == 0) {
        int flag = 1;
        #pragma unroll 1
        for (int i = 0; i < 64; i++) {
            if (ei32[2 * i + 1] != 0) { flag = 0; break; }
        }
        g_is64 = flag;   // 1 => int64 little-endian with zero high words
    }
}

__device__ __forceinline__ int load_idx(const void* ei, int i, int is64) {
    if (is64) return (int)((const long long*)ei)[i];
    return ((const int*)ei)[i];
}

// ---------------- init ----------------
__global__ void k_zero(int n) {
    int t = blockIdx.x * blockDim.x + threadIdx.x;
    if (t < n) { g_deg[t] = 0; g_cursor[t] = 0; }
}

// ---------------- layer-1 GEMM: xp = x @ W1  (M x 256) @ (256 x 256) ----------------
__global__ void k_gemm1(const float* __restrict__ X, const float* __restrict__ W, int M) {
    const int BM = 128, BN = 64, BK = 16;
    __shared__ float As[BK][BM + 4];
    __shared__ float Bs[BK][BN + 4];
    int t  = threadIdx.x;          // 256 threads
    int tx = t & 15, ty = t >> 4;  // 16 x 16
    int rowBase = blockIdx.x * BM;
    int colBase = blockIdx.y * BN;

    float acc[8][4];
    #pragma unroll
    for (int i = 0; i < 8; i++)
        #pragma unroll
        for (int j = 0; j < 4; j++) acc[i][j] = 0.f;

    for (int kt = 0; kt < 256; kt += BK) {
        // load A tile (128 x 16): 512 float4 total
        #pragma unroll
        for (int l = 0; l < 2; l++) {
            int q  = t + l * 256;
            int r  = q >> 2;
            int kq = (q & 3) * 4;
            int grow = rowBase + r;
            float4 v = make_float4(0.f, 0.f, 0.f, 0.f);
            if (grow < M) v = *(const float4*)(X + grow * 256 + kt + kq);
            As[kq + 0][r] = v.x; As[kq + 1][r] = v.y;
            As[kq + 2][r] = v.z; As[kq + 3][r] = v.w;
        }
        // load B tile (16 x 64): 256 float4
        {
            int r  = t >> 4;
            int c4 = (t & 15) * 4;
            float4 v = *(const float4*)(W + (kt + r) * 256 + colBase + c4);
            Bs[r][c4 + 0] = v.x; Bs[r][c4 + 1] = v.y;
            Bs[r][c4 + 2] = v.z; Bs[r][c4 + 3] = v.w;
        }
        __syncthreads();
        #pragma unroll
        for (int k = 0; k < BK; k++) {
            float a[8], b[4];
            #pragma unroll
            for (int i = 0; i < 8; i++) a[i] = As[k][ty * 8 + i];
            #pragma unroll
            for (int j = 0; j < 4; j++) b[j] = Bs[k][tx * 4 + j];
            #pragma unroll
            for (int i = 0; i < 8; i++)
                #pragma unroll
                for (int j = 0; j < 4; j++)
                    acc[i][j] = fmaf(a[i], b[j], acc[i][j]);
        }
        __syncthreads();
    }
    #pragma unroll
    for (int i = 0; i < 8; i++) {
        int grow = rowBase + ty * 8 + i;
        if (grow < M) {
            float4 v = make_float4(acc[i][0], acc[i][1], acc[i][2], acc[i][3]);
            *(float4*)(g_xp + (size_t)grow * 256 + colBase + tx * 4) = v;
        }
    }
}

// ---------------- per-node attention logits (layer 1) ----------------
__global__ void k_alpha1(const float* __restrict__ A_src, const float* __restrict__ A_dst, int n) {
    int w    = (blockIdx.x * blockDim.x + threadIdx.x) >> 5;
    int lane = threadIdx.x & 31;
    if (w >= n) return;
    const float* xr = g_xp + (size_t)w * 256 + lane;
    float ss[8], sd[8];
    #pragma unroll
    for (int h = 0; h < 8; h++) {
        float v = xr[h * 32];
        ss[h] = v * A_src[h * 32 + lane];
        sd[h] = v * A_dst[h * 32 + lane];
    }
    #pragma unroll
    for (int off = 16; off; off >>= 1)
        #pragma unroll
        for (int h = 0; h < 8; h++) {
            ss[h] += __shfl_xor_sync(0xffffffffu, ss[h], off);
            sd[h] += __shfl_xor_sync(0xffffffffu, sd[h], off);
        }
    if (lane == 0) {
        #pragma unroll
        for (int h = 0; h < 8; h++) {
            g_asrc[w * 8 + h] = ss[h];
            g_adst[w * 8 + h] = sd[h];
        }
    }
}

// ---------------- CSR build ----------------
__global__ void k_hist(const void* __restrict__ ei, int e) {
    int t = blockIdx.x * blockDim.x + threadIdx.x;
    if (t < e) {
        int dst = load_idx(ei, e + t, g_is64);
        atomicAdd(&g_deg[dst], 1);
    }
}

__global__ void k_scan(int n) {
    __shared__ int sums[1024];
    int tid = threadIdx.x;
    int chunk = (n + 1023) / 1024;
    int start = min(tid * chunk, n);
    int end   = min(start + chunk, n);
    int s = 0;
    for (int i = start; i < end; i++) s += g_deg[i] + 1;   // +1 self loop
    sums[tid] = s;
    __syncthreads();
    for (int off = 1; off < 1024; off <<= 1) {
        int v = (tid >= off) ? sums[tid - off] : 0;
        __syncthreads();
        sums[tid] += v;
        __syncthreads();
    }
    int run = (tid > 0) ? sums[tid - 1] : 0;
    for (int i = start; i < end; i++) {
        g_rowstart[i] = run;
        run += g_deg[i] + 1;
    }
    if (tid == 0) g_rowstart[n] = sums[1023];
}

__global__ void k_scatter(const void* __restrict__ ei, int e, int n) {
    int t = blockIdx.x * blockDim.x + threadIdx.x;
    if (t < e) {
        int is64 = g_is64;
        int src = load_idx(ei, t, is64);
        int dst = load_idx(ei, e + t, is64);
        int p = atomicAdd(&g_cursor[dst], 1);
        g_csr[g_rowstart[dst] + p] = src;
    } else if (t < e + n) {
        int node = t - e;
        int p = atomicAdd(&g_cursor[node], 1);
        g_csr[g_rowstart[node] + p] = node;     // self loop
    }
}

// ---------------- layer-1 aggregation (warp per node, 2-phase softmax) ----------------
__global__ void k_agg1(const float* __restrict__ b1, int n) {
    int w    = (blockIdx.x * blockDim.x + threadIdx.x) >> 5;
    int lane = threadIdx.x & 31;
    int wib  = threadIdx.x >> 5;
    __shared__ float sm[8][8];
    if (w >= n) return;
    int row = g_rowstart[w], end = g_rowstart[w + 1];

    float adn[8];
    #pragma unroll
    for (int h = 0; h < 8; h++) adn[h] = g_adst[w * 8 + h];

    // phase 1: per-head max over incoming edges
    float m[8];
    #pragma unroll
    for (int h = 0; h < 8; h++) m[h] = -1e30f;
    for (int j = row + lane; j < end; j += 32) {
        int src = g_csr[j];
        const float* ar = g_asrc + src * 8;
        #pragma unroll
        for (int h = 0; h < 8; h++) {
            float e = ar[h] + adn[h];
            e = fmaxf(e, 0.2f * e);       // leaky relu
            m[h] = fmaxf(m[h], e);
        }
    }
    #pragma unroll
    for (int off = 16; off; off >>= 1)
        #pragma unroll
        for (int h = 0; h < 8; h++)
            m[h] = fmaxf(m[h], __shfl_xor_sync(0xffffffffu, m[h], off));
    if (lane == 0) {
        #pragma unroll
        for (int h = 0; h < 8; h++) sm[wib][h] = m[h];
    }
    __syncwarp();
    float mh  = (lane < 8) ? sm[wib][lane] : 0.f;
    float adl = (lane < 8) ? g_adst[w * 8 + lane] : 0.f;

    // phase 2: exp/sum + weighted accumulate (lane = channel within each head)
    float s = 0.f;
    float acc[8] = {0.f, 0.f, 0.f, 0.f, 0.f, 0.f, 0.f, 0.f};
    for (int j = row; j < end; j++) {
        int src = g_csr[j];               // warp-uniform broadcast
        float p = 0.f;
        if (lane < 8) {
            float e = g_asrc[src * 8 + lane] + adl;
            e = fmaxf(e, 0.2f * e);
            p = __expf(e - mh);
            s += p;
        }
        const float* xr = g_xp + (size_t)src * 256 + lane;
        #pragma unroll
        for (int h = 0; h < 8; h++) {
            float ph = __shfl_sync(0xffffffffu, p, h);
            acc[h] = fmaf(xr[h * 32], ph, acc[h]);
        }
    }
    #pragma unroll
    for (int h = 0; h < 8; h++) {
        float sh = __shfl_sync(0xffffffffu, s, h);
        float v  = acc[h] / sh + b1[h * 32 + lane];
        g_h[(size_t)w * 256 + h * 32 + lane] = fmaxf(v, 0.f);
    }
}

// ---------------- layer-2 projection + attention logits ----------------
__global__ void k_gemm2a(const float* __restrict__ W2, const float* __restrict__ as2w,
                         const float* __restrict__ ad2w, int n) {
    int w    = (blockIdx.x * blockDim.x + threadIdx.x) >> 5;
    int lane = threadIdx.x & 31;
    if (w >= n) return;
    const float* hr = g_h + (size_t)w * 256 + lane;
    float o0 = 0.f, o1 = 0.f;
    #pragma unroll
    for (int i = 0; i < 8; i++) {
        float v = hr[i * 32];
        int k = lane + i * 32;
        o0 = fmaf(v, W2[k * 2 + 0], o0);
        o1 = fmaf(v, W2[k * 2 + 1], o1);
    }
    #pragma unroll
    for (int off = 16; off; off >>= 1) {
        o0 += __shfl_xor_sync(0xffffffffu, o0, off);
        o1 += __shfl_xor_sync(0xffffffffu, o1, off);
    }
    if (lane == 0) {
        g_hp[w * 2 + 0] = o0;
        g_hp[w * 2 + 1] = o1;
        g_as2[w] = o0 * as2w[0] + o1 * as2w[1];
        g_ad2[w] = o0 * ad2w[0] + o1 * ad2w[1];
    }
}

// ---------------- layer-2 aggregation (warp per node, online softmax per lane) --------
__global__ void k_agg2(const float* __restrict__ b2, float* __restrict__ out, int n) {
    int w    = (blockIdx.x * blockDim.x + threadIdx.x) >> 5;
    int lane = threadIdx.x & 31;
    if (w >= n) return;
    int row = g_rowstart[w], end = g_rowstart[w + 1];
    float adn = g_ad2[w];

    float m = -INFINITY, s = 0.f, a0 = 0.f, a1 = 0.f;
    for (int j = row + lane; j < end; j += 32) {
        int src = g_csr[j];
        float e = g_as2[src] + adn;
        e = fmaxf(e, 0.2f * e);
        float mn   = fmaxf(m, e);
        float corr = __expf(m - mn);      // m=-inf -> 0 (mn finite)
        float p    = __expf(e - mn);
        s  = s * corr + p;
        a0 = a0 * corr + g_hp[src * 2 + 0] * p;
        a1 = a1 * corr + g_hp[src * 2 + 1] * p;
        m  = mn;
    }
    #pragma unroll
    for (int off = 16; off; off >>= 1) {
        float mo  = __shfl_xor_sync(0xffffffffu, m,  off);
        float so  = __shfl_xor_sync(0xffffffffu, s,  off);
        float a0o = __shfl_xor_sync(0xffffffffu, a0, off);
        float a1o = __shfl_xor_sync(0xffffffffu, a1, off);
        float mn = fmaxf(m, mo);
        float c1 = (m  == mn) ? 1.f : __expf(m  - mn);
        float c2 = (mo == mn) ? 1.f : __expf(mo - mn);
        s  = s * c1 + so * c2;
        a0 = a0 * c1 + a0o * c2;
        a1 = a1 * c1 + a1o * c2;
        m  = mn;
    }
    if (lane == 0) {
        out[w * 2 + 0] = a0 / s + b2[0];
        out[w * 2 + 1] = a1 / s + b2[1];
    }
}

// ---------------- launch ----------------
extern "C" void kernel_launch(void* const* d_in, const int* in_sizes, int n_in,
                              void* d_out, int out_size) {
    const float* x   = (const float*)d_in[0];
    const void*  ei  = d_in[1];                 // int64 or int32, detected on device
    const float* W1  = (const float*)d_in[2];
    const float* as1 = (const float*)d_in[3];
    const float* ad1 = (const float*)d_in[4];
    const float* b1  = (const float*)d_in[5];
    const float* W2  = (const float*)d_in[6];
    const float* as2 = (const float*)d_in[7];
    const float* ad2 = (const float*)d_in[8];
    const float* b2  = (const float*)d_in[9];

    int n = in_sizes[0] / 256;   // 50000
    int e = in_sizes[1] / 2;     // 800000

    int warpBlocks = (n * 32 + 255) / 256;

    k_detect<<<1, 32>>>((const int*)ei);
    k_zero<<<(n + 255) / 256, 256>>>(n);

    dim3 gg((n + 127) / 128, 4);
    k_gemm1<<<gg, 256>>>(x, W1, n);
    k_alpha1<<<warpBlocks, 256>>>(as1, ad1, n);

    k_hist<<<(e + 255) / 256, 256>>>(ei, e);
    k_scan<<<1, 1024>>>(n);
    k_scatter<<<(e + n + 255) / 256, 256>>>(ei, e, n);

    k_agg1<<<warpBlocks, 256>>>(b1, n);
    k_gemm2a<<<warpBlocks, 256>>>(W2, as2, ad2, n);
    k_agg2<<<warpBlocks, 256>>>(b2, (float*)d_out, n);
}

// round 2
// speedup vs baseline: 1.0674x; 1.0674x over previous
#include <cuda_runtime.h>
#include <cuda_fp16.h>
#include <math.h>

#define NMAX 50000
#define EMAX 800000
#define TOT_E (EMAX + NMAX)

typedef unsigned long long ull;

// ---------------- scratch (static __device__, no allocs) ----------------
__device__ __half g_xph[NMAX * 256];    // layer-1 projected features (fp16 storage)
__device__ __half g_hh[NMAX * 256];     // layer-1 output relu (fp16 storage)
__device__ float  g_asrc[NMAX * 8];
__device__ float  g_adst[NMAX * 8];
__device__ int    g_deg[NMAX];
__device__ int    g_rowstart[NMAX + 1];
__device__ int    g_cursor[NMAX];
__device__ int    g_csr[TOT_E];
__device__ float  g_hp[NMAX * 2];
__device__ float  g_as2[NMAX];
__device__ float  g_ad2[NMAX];
__device__ int    g_is64;

// ---------------- f32x2 packed helpers (Blackwell FFMA2) ----------------
__device__ __forceinline__ ull pk2(float x, float y) {
    ull r; asm("mov.b64 %0, {%1,%2};" : "=l"(r) : "f"(x), "f"(y)); return r;
}
__device__ __forceinline__ void fma2(ull& d, ull a, ull b) {
    asm("fma.rn.f32x2 %0, %1, %2, %0;" : "+l"(d) : "l"(a), "l"(b));
}
__device__ __forceinline__ float2 upk2(ull v) {
    float2 f; asm("mov.b64 {%0,%1}, %2;" : "=f"(f.x), "=f"(f.y) : "l"(v)); return f;
}

// ---------------- edge-index dtype detection ----------------
__global__ void k_detect(const int* __restrict__ ei32) {
    if (blockIdx.x == 0 && threadIdx.x == 0) {
        int flag = 1;
        #pragma unroll 1
        for (int i = 0; i < 64; i++) {
            if (ei32[2 * i + 1] != 0) { flag = 0; break; }
        }
        g_is64 = flag;
    }
}

__device__ __forceinline__ int load_idx(const void* ei, int i, int is64) {
    if (is64) return (int)((const long long*)ei)[i];
    return ((const int*)ei)[i];
}

__global__ void k_zero(int n) {
    int t = blockIdx.x * blockDim.x + threadIdx.x;
    if (t < n) { g_deg[t] = 0; g_cursor[t] = 0; }
}

// ---------------- layer-1 GEMM: xp = x @ W1, fp16 out, FFMA2 inner ----------------
// 128x128x16 tiles, 256 threads, 8x8 per-thread tile (pair-packed cols)
__global__ void __launch_bounds__(256, 2) k_gemm1(const float* __restrict__ X,
                                                  const float* __restrict__ W, int M) {
    const int BM = 128, BK = 16;
    __shared__ float As[BK][BM + 4];   // stride 132 floats (16B aligned)
    __shared__ float Bs[BK][BM + 4];
    int t  = threadIdx.x;
    int tx = t & 15, ty = t >> 4;
    int rowBase = blockIdx.x * BM;
    int colBase = blockIdx.y * BM;

    ull acc[8][4];
    #pragma unroll
    for (int i = 0; i < 8; i++)
        #pragma unroll
        for (int j = 0; j < 4; j++) acc[i][j] = 0ull;

    for (int kt = 0; kt < 256; kt += BK) {
        // A tile (128 rows x 16 k): 512 float4, 2 per thread, transposed into As
        #pragma unroll
        for (int l = 0; l < 2; l++) {
            int idx = t + l * 256;
            int r   = idx >> 2;
            int kq  = (idx & 3) * 4;
            int grow = rowBase + r;
            float4 v = make_float4(0.f, 0.f, 0.f, 0.f);
            if (grow < M) v = *(const float4*)(X + (size_t)grow * 256 + kt + kq);
            As[kq + 0][r] = v.x; As[kq + 1][r] = v.y;
            As[kq + 2][r] = v.z; As[kq + 3][r] = v.w;
        }
        // B tile (16 k x 128 cols): 512 float4, coalesced
        #pragma unroll
        for (int l = 0; l < 2; l++) {
            int idx = t + l * 256;
            int r   = idx >> 5;
            int c4  = (idx & 31) * 4;
            float4 v = *(const float4*)(W + (size_t)(kt + r) * 256 + colBase + c4);
            *(float4*)&Bs[r][c4] = v;
        }
        __syncthreads();
        #pragma unroll
        for (int k = 0; k < BK; k++) {
            float4 a0 = *(const float4*)&As[k][ty * 4];
            float4 a1 = *(const float4*)&As[k][64 + ty * 4];
            float4 b0 = *(const float4*)&Bs[k][tx * 4];
            float4 b1 = *(const float4*)&Bs[k][64 + tx * 4];
            ull bp[4] = { pk2(b0.x, b0.y), pk2(b0.z, b0.w),
                          pk2(b1.x, b1.y), pk2(b1.z, b1.w) };
            float av[8] = { a0.x, a0.y, a0.z, a0.w, a1.x, a1.y, a1.z, a1.w };
            #pragma unroll
            for (int i = 0; i < 8; i++) {
                ull aa = pk2(av[i], av[i]);
                #pragma unroll
                for (int j = 0; j < 4; j++) fma2(acc[i][j], aa, bp[j]);
            }
        }
        __syncthreads();
    }
    // epilogue: fp16 store
    #pragma unroll
    for (int i = 0; i < 8; i++) {
        int ri   = (i < 4) ? (ty * 4 + i) : (64 + ty * 4 + (i - 4));
        int grow = rowBase + ri;
        if (grow >= M) continue;
        #pragma unroll
        for (int j = 0; j < 4; j++) {
            int c = (j < 2) ? (tx * 4 + 2 * j) : (64 + tx * 4 + 2 * (j - 2));
            float2 f = upk2(acc[i][j]);
            *reinterpret_cast<__half2*>(g_xph + (size_t)grow * 256 + colBase + c) =
                __floats2half2_rn(f.x, f.y);
        }
    }
}

// ---------------- per-node attention logits (layer 1), fp16 xp ----------------
__global__ void k_alpha1(const float* __restrict__ A_src, const float* __restrict__ A_dst, int n) {
    int w    = (blockIdx.x * blockDim.x + threadIdx.x) >> 5;
    int lane = threadIdx.x & 31;
    if (w >= n) return;
    const __half* xr = g_xph + (size_t)w * 256 + lane;
    float ss[8], sd[8];
    #pragma unroll
    for (int h = 0; h < 8; h++) {
        float v = __half2float(xr[h * 32]);
        ss[h] = v * A_src[h * 32 + lane];
        sd[h] = v * A_dst[h * 32 + lane];
    }
    #pragma unroll
    for (int off = 16; off; off >>= 1)
        #pragma unroll
        for (int h = 0; h < 8; h++) {
            ss[h] += __shfl_xor_sync(0xffffffffu, ss[h], off);
            sd[h] += __shfl_xor_sync(0xffffffffu, sd[h], off);
        }
    if (lane == 0) {
        #pragma unroll
        for (int h = 0; h < 8; h++) {
            g_asrc[w * 8 + h] = ss[h];
            g_adst[w * 8 + h] = sd[h];
        }
    }
}

// ---------------- CSR build ----------------
__global__ void k_hist(const void* __restrict__ ei, int e) {
    int t = blockIdx.x * blockDim.x + threadIdx.x;
    if (t < e) {
        int dst = load_idx(ei, e + t, g_is64);
        atomicAdd(&g_deg[dst], 1);
    }
}

__global__ void k_scan(int n) {
    __shared__ int sums[1024];
    int tid = threadIdx.x;
    int chunk = (n + 1023) / 1024;
    int start = min(tid * chunk, n);
    int end   = min(start + chunk, n);
    int s = 0;
    for (int i = start; i < end; i++) s += g_deg[i] + 1;
    sums[tid] = s;
    __syncthreads();
    for (int off = 1; off < 1024; off <<= 1) {
        int v = (tid >= off) ? sums[tid - off] : 0;
        __syncthreads();
        sums[tid] += v;
        __syncthreads();
    }
    int run = (tid > 0) ? sums[tid - 1] : 0;
    for (int i = start; i < end; i++) {
        g_rowstart[i] = run;
        run += g_deg[i] + 1;
    }
    if (tid == 0) g_rowstart[n] = sums[1023];
}

__global__ void k_scatter(const void* __restrict__ ei, int e, int n) {
    int t = blockIdx.x * blockDim.x + threadIdx.x;
    if (t < e) {
        int is64 = g_is64;
        int src = load_idx(ei, t, is64);
        int dst = load_idx(ei, e + t, is64);
        int p = atomicAdd(&g_cursor[dst], 1);
        g_csr[g_rowstart[dst] + p] = src;
    } else if (t < e + n) {
        int node = t - e;
        int p = atomicAdd(&g_cursor[node], 1);
        g_csr[g_rowstart[node] + p] = node;
    }
}

// ---------------- layer-1 aggregation (warp per node, 2-phase softmax) ----------------
__global__ void k_agg1(const float* __restrict__ b1, int n) {
    int w    = (blockIdx.x * blockDim.x + threadIdx.x) >> 5;
    int lane = threadIdx.x & 31;
    int wib  = threadIdx.x >> 5;
    __shared__ float sm[8][8];
    if (w >= n) return;
    int row = g_rowstart[w], end = g_rowstart[w + 1];

    float adn[8];
    #pragma unroll
    for (int h = 0; h < 8; h++) adn[h] = g_adst[w * 8 + h];

    float m[8];
    #pragma unroll
    for (int h = 0; h < 8; h++) m[h] = -1e30f;
    for (int j = row + lane; j < end; j += 32) {
        int src = g_csr[j];
        const float* ar = g_asrc + src * 8;
        #pragma unroll
        for (int h = 0; h < 8; h++) {
            float e = ar[h] + adn[h];
            e = fmaxf(e, 0.2f * e);
            m[h] = fmaxf(m[h], e);
        }
    }
    #pragma unroll
    for (int off = 16; off; off >>= 1)
        #pragma unroll
        for (int h = 0; h < 8; h++)
            m[h] = fmaxf(m[h], __shfl_xor_sync(0xffffffffu, m[h], off));
    if (lane == 0) {
        #pragma unroll
        for (int h = 0; h < 8; h++) sm[wib][h] = m[h];
    }
    __syncwarp();
    float mh  = (lane < 8) ? sm[wib][lane] : 0.f;
    float adl = (lane < 8) ? g_adst[w * 8 + lane] : 0.f;

    float s = 0.f;
    float acc[8] = {0.f, 0.f, 0.f, 0.f, 0.f, 0.f, 0.f, 0.f};
    for (int j = row; j < end; j++) {
        int src = g_csr[j];
        float p = 0.f;
        if (lane < 8) {
            float e = g_asrc[src * 8 + lane] + adl;
            e = fmaxf(e, 0.2f * e);
            p = __expf(e - mh);
            s += p;
        }
        const __half* xr = g_xph + (size_t)src * 256 + lane;
        #pragma unroll
        for (int h = 0; h < 8; h++) {
            float ph = __shfl_sync(0xffffffffu, p, h);
            acc[h] = fmaf(__half2float(xr[h * 32]), ph, acc[h]);
        }
    }
    #pragma unroll
    for (int h = 0; h < 8; h++) {
        float sh = __shfl_sync(0xffffffffu, s, h);
        float v  = acc[h] / sh + b1[h * 32 + lane];
        g_hh[(size_t)w * 256 + h * 32 + lane] = __float2half(fmaxf(v, 0.f));
    }
}

// ---------------- layer-2 projection + attention logits ----------------
__global__ void k_gemm2a(const float* __restrict__ W2, const float* __restrict__ as2w,
                         const float* __restrict__ ad2w, int n) {
    int w    = (blockIdx.x * blockDim.x + threadIdx.x) >> 5;
    int lane = threadIdx.x & 31;
    if (w >= n) return;
    const __half* hr = g_hh + (size_t)w * 256 + lane;
    float o0 = 0.f, o1 = 0.f;
    #pragma unroll
    for (int i = 0; i < 8; i++) {
        float v = __half2float(hr[i * 32]);
        int k = lane + i * 32;
        o0 = fmaf(v, W2[k * 2 + 0], o0);
        o1 = fmaf(v, W2[k * 2 + 1], o1);
    }
    #pragma unroll
    for (int off = 16; off; off >>= 1) {
        o0 += __shfl_xor_sync(0xffffffffu, o0, off);
        o1 += __shfl_xor_sync(0xffffffffu, o1, off);
    }
    if (lane == 0) {
        g_hp[w * 2 + 0] = o0;
        g_hp[w * 2 + 1] = o1;
        g_as2[w] = o0 * as2w[0] + o1 * as2w[1];
        g_ad2[w] = o0 * ad2w[0] + o1 * ad2w[1];
    }
}

// ---------------- layer-2 aggregation ----------------
__global__ void k_agg2(const float* __restrict__ b2, float* __restrict__ out, int n) {
    int w    = (blockIdx.x * blockDim.x + threadIdx.x) >> 5;
    int lane = threadIdx.x & 31;
    if (w >= n) return;
    int row = g_rowstart[w], end = g_rowstart[w + 1];
    float adn = g_ad2[w];

    float m = -INFINITY, s = 0.f, a0 = 0.f, a1 = 0.f;
    for (int j = row + lane; j < end; j += 32) {
        int src = g_csr[j];
        float e = g_as2[src] + adn;
        e = fmaxf(e, 0.2f * e);
        float mn   = fmaxf(m, e);
        float corr = __expf(m - mn);
        float p    = __expf(e - mn);
        s  = s * corr + p;
        a0 = a0 * corr + g_hp[src * 2 + 0] * p;
        a1 = a1 * corr + g_hp[src * 2 + 1] * p;
        m  = mn;
    }
    #pragma unroll
    for (int off = 16; off; off >>= 1) {
        float mo  = __shfl_xor_sync(0xffffffffu, m,  off);
        float so  = __shfl_xor_sync(0xffffffffu, s,  off);
        float a0o = __shfl_xor_sync(0xffffffffu, a0, off);
        float a1o = __shfl_xor_sync(0xffffffffu, a1, off);
        float mn = fmaxf(m, mo);
        float c1 = (m  == mn) ? 1.f : __expf(m  - mn);
        float c2 = (mo == mn) ? 1.f : __expf(mo - mn);
        s  = s * c1 + so * c2;
        a0 = a0 * c1 + a0o * c2;
        a1 = a1 * c1 + a1o * c2;
        m  = mn;
    }
    if (lane == 0) {
        out[w * 2 + 0] = a0 / s + b2[0];
        out[w * 2 + 1] = a1 / s + b2[1];
    }
}

// ---------------- launch ----------------
extern "C" void kernel_launch(void* const* d_in, const int* in_sizes, int n_in,
                              void* d_out, int out_size) {
    const float* x   = (const float*)d_in[0];
    const void*  ei  = d_in[1];
    const float* W1  = (const float*)d_in[2];
    const float* as1 = (const float*)d_in[3];
    const float* ad1 = (const float*)d_in[4];
    const float* b1  = (const float*)d_in[5];
    const float* W2  = (const float*)d_in[6];
    const float* as2 = (const float*)d_in[7];
    const float* ad2 = (const float*)d_in[8];
    const float* b2  = (const float*)d_in[9];

    int n = in_sizes[0] / 256;
    int e = in_sizes[1] / 2;

    int warpBlocks = (n * 32 + 255) / 256;

    k_detect<<<1, 32>>>((const int*)ei);
    k_zero<<<(n + 255) / 256, 256>>>(n);

    dim3 gg((n + 127) / 128, 2);
    k_gemm1<<<gg, 256>>>(x, W1, n);
    k_alpha1<<<warpBlocks, 256>>>(as1, ad1, n);

    k_hist<<<(e + 255) / 256, 256>>>(ei, e);
    k_scan<<<1, 1024>>>(n);
    k_scatter<<<(e + n + 255) / 256, 256>>>(ei, e, n);

    k_agg1<<<warpBlocks, 256>>>(b1, n);
    k_gemm2a<<<warpBlocks, 256>>>(W2, as2, ad2, n);
    k_agg2<<<warpBlocks, 256>>>(b2, (float*)d_out, n);
}

// round 3
// speedup vs baseline: 1.6116x; 1.5099x over previous
#include <cuda_runtime.h>
#include <cuda_fp16.h>
#include <math.h>
#include <stdint.h>

#define NMAX 50000
#define EMAX 800000
#define TOT_E (EMAX + NMAX)

// ---------------- scratch ----------------
__device__ __half g_xph[NMAX * 256];
__device__ __half g_hh[NMAX * 256];
__device__ float  g_asrc[NMAX * 8];
__device__ float  g_adst[NMAX * 8];
__device__ int    g_deg[NMAX];
__device__ int    g_rowstart[NMAX + 1];
__device__ int    g_cursor[NMAX];
__device__ int    g_csr[TOT_E];
__device__ float  g_hp[NMAX * 2];
__device__ float  g_as2[NMAX];
__device__ float  g_ad2[NMAX];
__device__ int    g_is64;

// ---------------- mma helpers ----------------
__device__ __forceinline__ uint32_t sptr(const void* p) {
    return (uint32_t)__cvta_generic_to_shared(p);
}
__device__ __forceinline__ void ldsm4(uint32_t* r, uint32_t a) {
    asm volatile("ldmatrix.sync.aligned.m8n8.x4.shared.b16 {%0,%1,%2,%3},[%4];"
        : "=r"(r[0]), "=r"(r[1]), "=r"(r[2]), "=r"(r[3]) : "r"(a));
}
__device__ __forceinline__ void ldsm4t(uint32_t* r, uint32_t a) {
    asm volatile("ldmatrix.sync.aligned.m8n8.x4.trans.shared.b16 {%0,%1,%2,%3},[%4];"
        : "=r"(r[0]), "=r"(r[1]), "=r"(r[2]), "=r"(r[3]) : "r"(a));
}
__device__ __forceinline__ void mma16816(float* c, const uint32_t* a, uint32_t b0, uint32_t b1) {
    asm volatile(
        "mma.sync.aligned.m16n8k16.row.col.f32.f16.f16.f32 "
        "{%0,%1,%2,%3},{%4,%5,%6,%7},{%8,%9},{%0,%1,%2,%3};"
        : "+f"(c[0]), "+f"(c[1]), "+f"(c[2]), "+f"(c[3])
        : "r"(a[0]), "r"(a[1]), "r"(a[2]), "r"(a[3]), "r"(b0), "r"(b1));
}

__device__ __forceinline__ int load_idx(const void* ei, int i, int is64) {
    if (is64) return (int)((const long long*)ei)[i];
    return ((const int*)ei)[i];
}

// ---------------- init: zero counters + parallel dtype detect ----------------
__global__ void k_init(const int* __restrict__ ei32, int n) {
    int t = blockIdx.x * blockDim.x + threadIdx.x;
    if (t < n) { g_deg[t] = 0; g_cursor[t] = 0; }
    if (blockIdx.x == 0 && threadIdx.x < 32) {
        int bad = 0;
        #pragma unroll
        for (int i = threadIdx.x; i < 64; i += 32)
            bad |= (ei32[2 * i + 1] != 0);
        unsigned m = __ballot_sync(0xffffffffu, bad);
        if (threadIdx.x == 0) g_is64 = (m == 0);
    }
}

// ---------------- layer-1 GEMM: xp(fp16) = fp16(x) @ fp16(W1), HMMA ----------------
// 128x128x32 tiles, 256 threads (8 warps as 4x2), warp tile 32x64
__global__ void __launch_bounds__(256, 2) k_gemm1(const float* __restrict__ X,
                                                  const float* __restrict__ W, int M) {
    const int BM = 128, BK = 32;
    __shared__ __half As[BM][40];    // stride 80B (mult of 16; conflict-free for ldsm)
    __shared__ __half Bs[BK][136];   // stride 272B
    int t    = threadIdx.x;
    int wid  = t >> 5, lane = t & 31;
    int lr   = lane & 7, lg = lane >> 3;
    int wm   = (wid >> 1) * 32;
    int wn   = (wid & 1) * 64;
    int rowBase = blockIdx.x * BM;
    int colBase = blockIdx.y * BM;

    float c[2][8][4];
    #pragma unroll
    for (int i = 0; i < 2; i++)
        #pragma unroll
        for (int j = 0; j < 8; j++)
            #pragma unroll
            for (int k = 0; k < 4; k++) c[i][j][k] = 0.f;

    for (int kt = 0; kt < 256; kt += BK) {
        // A tile: 128 rows x 32 k (fp32 -> fp16)
        #pragma unroll
        for (int i = 0; i < 4; i++) {
            int q = t + i * 256;
            int r = q >> 3, kq = (q & 7) * 4;
            int grow = rowBase + r;
            float4 v = make_float4(0.f, 0.f, 0.f, 0.f);
            if (grow < M) v = *(const float4*)(X + (size_t)grow * 256 + kt + kq);
            *(__half2*)&As[r][kq]     = __floats2half2_rn(v.x, v.y);
            *(__half2*)&As[r][kq + 2] = __floats2half2_rn(v.z, v.w);
        }
        // B tile: 32 k x 128 cols
        #pragma unroll
        for (int i = 0; i < 4; i++) {
            int q = t + i * 256;
            int r = q >> 5, c4 = (q & 31) * 4;
            float4 v = *(const float4*)(W + (size_t)(kt + r) * 256 + colBase + c4);
            *(__half2*)&Bs[r][c4]     = __floats2half2_rn(v.x, v.y);
            *(__half2*)&Bs[r][c4 + 2] = __floats2half2_rn(v.z, v.w);
        }
        __syncthreads();
        #pragma unroll
        for (int ks = 0; ks < 2; ks++) {
            uint32_t a[2][4], b[4][4];
            #pragma unroll
            for (int mt = 0; mt < 2; mt++) {
                int row = wm + mt * 16 + lr + (lg & 1) * 8;
                int col = ks * 16 + (lg >> 1) * 8;
                ldsm4(a[mt], sptr(&As[row][col]));
            }
            #pragma unroll
            for (int ng = 0; ng < 4; ng++) {
                int krow = ks * 16 + lr + (lg & 1) * 8;
                int col  = wn + ng * 16 + (lg >> 1) * 8;
                ldsm4t(b[ng], sptr(&Bs[krow][col]));
            }
            #pragma unroll
            for (int mt = 0; mt < 2; mt++)
                #pragma unroll
                for (int nt = 0; nt < 8; nt++)
                    mma16816(c[mt][nt], a[mt], b[nt >> 1][(nt & 1) * 2],
                             b[nt >> 1][(nt & 1) * 2 + 1]);
        }
        __syncthreads();
    }
    // epilogue: fp16 store
    #pragma unroll
    for (int mt = 0; mt < 2; mt++) {
        int r0 = rowBase + wm + mt * 16 + (lane >> 2);
        #pragma unroll
        for (int nt = 0; nt < 8; nt++) {
            int col = colBase + wn + nt * 8 + (lane & 3) * 2;
            if (r0 < M)
                *(__half2*)(g_xph + (size_t)r0 * 256 + col) =
                    __floats2half2_rn(c[mt][nt][0], c[mt][nt][1]);
            if (r0 + 8 < M)
                *(__half2*)(g_xph + (size_t)(r0 + 8) * 256 + col) =
                    __floats2half2_rn(c[mt][nt][2], c[mt][nt][3]);
        }
    }
}

// ---------------- per-node attention logits, half2 col-ownership ----------------
__global__ void k_alpha1(const float* __restrict__ A_src, const float* __restrict__ A_dst, int n) {
    int w    = (blockIdx.x * blockDim.x + threadIdx.x) >> 5;
    int lane = threadIdx.x & 31;
    if (w >= n) return;
    const __half2* xr = (const __half2*)(g_xph + (size_t)w * 256);
    float s[4], d[4];
    #pragma unroll
    for (int i = 0; i < 4; i++) {
        int cidx = lane + i * 32;          // half2 col, head = cidx>>4
        int head = cidx >> 4;
        int lc   = (cidx & 15) * 2;
        float2 v  = __half22float2(xr[cidx]);
        float2 ws = *(const float2*)(A_src + head * 32 + lc);
        float2 wd = *(const float2*)(A_dst + head * 32 + lc);
        s[i] = v.x * ws.x + v.y * ws.y;
        d[i] = v.x * wd.x + v.y * wd.y;
    }
    #pragma unroll
    for (int off = 8; off; off >>= 1)
        #pragma unroll
        for (int i = 0; i < 4; i++) {
            s[i] += __shfl_xor_sync(0xffffffffu, s[i], off);
            d[i] += __shfl_xor_sync(0xffffffffu, d[i], off);
        }
    if ((lane & 15) == 0) {
        int hb = lane >> 4;                // lanes 0..15 -> even heads, 16..31 -> odd
        #pragma unroll
        for (int i = 0; i < 4; i++) {
            g_asrc[w * 8 + i * 2 + hb] = s[i];
            g_adst[w * 8 + i * 2 + hb] = d[i];
        }
    }
}

// ---------------- CSR build ----------------
__global__ void k_hist(const void* __restrict__ ei, int e) {
    int t = blockIdx.x * blockDim.x + threadIdx.x;
    if (t < e) {
        int dst = load_idx(ei, e + t, g_is64);
        atomicAdd(&g_deg[dst], 1);
    }
}

__global__ void k_scan(int n) {
    __shared__ int sums[1024];
    int tid = threadIdx.x;
    int chunk = (n + 1023) / 1024;
    int start = min(tid * chunk, n);
    int end   = min(start + chunk, n);
    int s = 0;
    for (int i = start; i < end; i++) s += g_deg[i] + 1;
    sums[tid] = s;
    __syncthreads();
    for (int off = 1; off < 1024; off <<= 1) {
        int v = (tid >= off) ? sums[tid - off] : 0;
        __syncthreads();
        sums[tid] += v;
        __syncthreads();
    }
    int run = (tid > 0) ? sums[tid - 1] : 0;
    for (int i = start; i < end; i++) {
        g_rowstart[i] = run;
        run += g_deg[i] + 1;
    }
    if (tid == 0) g_rowstart[n] = sums[1023];
}

__global__ void k_scatter(const void* __restrict__ ei, int e, int n) {
    int t = blockIdx.x * blockDim.x + threadIdx.x;
    if (t < e) {
        int is64 = g_is64;
        int src = load_idx(ei, t, is64);
        int dst = load_idx(ei, e + t, is64);
        int p = atomicAdd(&g_cursor[dst], 1);
        g_csr[g_rowstart[dst] + p] = src;
    } else if (t < e + n) {
        int node = t - e;
        int p = atomicAdd(&g_cursor[node], 1);
        g_csr[g_rowstart[node] + p] = node;
    }
}

// ---------------- layer-1 aggregation ----------------
__global__ void k_agg1(const float* __restrict__ b1, int n) {
    int w    = (blockIdx.x * blockDim.x + threadIdx.x) >> 5;
    int lane = threadIdx.x & 31;
    int wib  = threadIdx.x >> 5;
    __shared__ float sm[8][8];
    if (w >= n) return;
    int row = g_rowstart[w], end = g_rowstart[w + 1];

    float adn[8];
    #pragma unroll
    for (int h = 0; h < 8; h++) adn[h] = g_adst[w * 8 + h];

    // phase 1: per-head max (float4 loads of asrc rows)
    float m[8];
    #pragma unroll
    for (int h = 0; h < 8; h++) m[h] = -1e30f;
    for (int j = row + lane; j < end; j += 32) {
        int src = g_csr[j];
        float4 a0 = *(const float4*)(g_asrc + (size_t)src * 8);
        float4 a1 = *(const float4*)(g_asrc + (size_t)src * 8 + 4);
        float ev[8] = {a0.x, a0.y, a0.z, a0.w, a1.x, a1.y, a1.z, a1.w};
        #pragma unroll
        for (int h = 0; h < 8; h++) {
            float e = ev[h] + adn[h];
            e = fmaxf(e, 0.2f * e);
            m[h] = fmaxf(m[h], e);
        }
    }
    #pragma unroll
    for (int off = 16; off; off >>= 1)
        #pragma unroll
        for (int h = 0; h < 8; h++)
            m[h] = fmaxf(m[h], __shfl_xor_sync(0xffffffffu, m[h], off));
    if (lane == 0) {
        #pragma unroll
        for (int h = 0; h < 8; h++) sm[wib][h] = m[h];
    }
    __syncwarp();
    float mh  = (lane < 8) ? sm[wib][lane] : 0.f;
    float adl = (lane < 8) ? adn[lane] : 0.f;

    // phase 2: lanes 0-7 compute p per head; lane owns half2 cols lane+32i
    int hidx[4];
    #pragma unroll
    for (int i = 0; i < 4; i++) hidx[i] = 2 * i + (lane >> 4);
    float s = 0.f;
    float2 acc[4] = {{0.f,0.f},{0.f,0.f},{0.f,0.f},{0.f,0.f}};
    for (int j = row; j < end; j++) {
        int src = g_csr[j];
        float p = 0.f;
        if (lane < 8) {
            float e = g_asrc[src * 8 + lane] + adl;
            e = fmaxf(e, 0.2f * e);
            p = __expf(e - mh);
            s += p;
        }
        const __half2* xr = (const __half2*)(g_xph + (size_t)src * 256);
        #pragma unroll
        for (int i = 0; i < 4; i++) {
            float ph = __shfl_sync(0xffffffffu, p, hidx[i]);
            float2 v = __half22float2(xr[lane + i * 32]);
            acc[i].x = fmaf(v.x, ph, acc[i].x);
            acc[i].y = fmaf(v.y, ph, acc[i].y);
        }
    }
    __half2* hw = (__half2*)(g_hh + (size_t)w * 256);
    #pragma unroll
    for (int i = 0; i < 4; i++) {
        float sh = __shfl_sync(0xffffffffu, s, hidx[i]);
        int cidx = lane + i * 32;
        float2 bb = *(const float2*)(b1 + 2 * cidx);
        float vx = fmaxf(acc[i].x / sh + bb.x, 0.f);
        float vy = fmaxf(acc[i].y / sh + bb.y, 0.f);
        hw[cidx] = __floats2half2_rn(vx, vy);
    }
}

// ---------------- layer-2 projection + attention logits ----------------
__global__ void k_gemm2a(const float* __restrict__ W2, const float* __restrict__ as2w,
                         const float* __restrict__ ad2w, int n) {
    int w    = (blockIdx.x * blockDim.x + threadIdx.x) >> 5;
    int lane = threadIdx.x & 31;
    if (w >= n) return;
    const __half2* hr = (const __half2*)(g_hh + (size_t)w * 256);
    float o0 = 0.f, o1 = 0.f;
    #pragma unroll
    for (int i = 0; i < 4; i++) {
        int cidx = lane + i * 32;
        float2 v = __half22float2(hr[cidx]);
        float4 w4 = *(const float4*)(W2 + 4 * cidx);   // rows 2c,2c+1 of [256][2]
        o0 += v.x * w4.x + v.y * w4.z;
        o1 += v.x * w4.y + v.y * w4.w;
    }
    #pragma unroll
    for (int off = 16; off; off >>= 1) {
        o0 += __shfl_xor_sync(0xffffffffu, o0, off);
        o1 += __shfl_xor_sync(0xffffffffu, o1, off);
    }
    if (lane == 0) {
        g_hp[w * 2 + 0] = o0;
        g_hp[w * 2 + 1] = o1;
        g_as2[w] = o0 * as2w[0] + o1 * as2w[1];
        g_ad2[w] = o0 * ad2w[0] + o1 * ad2w[1];
    }
}

// ---------------- layer-2 aggregation ----------------
__global__ void k_agg2(const float* __restrict__ b2, float* __restrict__ out, int n) {
    int w    = (blockIdx.x * blockDim.x + threadIdx.x) >> 5;
    int lane = threadIdx.x & 31;
    if (w >= n) return;
    int row = g_rowstart[w], end = g_rowstart[w + 1];
    float adn = g_ad2[w];

    float m = -INFINITY, s = 0.f, a0 = 0.f, a1 = 0.f;
    for (int j = row + lane; j < end; j += 32) {
        int src = g_csr[j];
        float e = g_as2[src] + adn;
        e = fmaxf(e, 0.2f * e);
        float mn   = fmaxf(m, e);
        float corr = __expf(m - mn);
        float p    = __expf(e - mn);
        s  = s * corr + p;
        a0 = a0 * corr + g_hp[src * 2 + 0] * p;
        a1 = a1 * corr + g_hp[src * 2 + 1] * p;
        m  = mn;
    }
    #pragma unroll
    for (int off = 16; off; off >>= 1) {
        float mo  = __shfl_xor_sync(0xffffffffu, m,  off);
        float so  = __shfl_xor_sync(0xffffffffu, s,  off);
        float a0o = __shfl_xor_sync(0xffffffffu, a0, off);
        float a1o = __shfl_xor_sync(0xffffffffu, a1, off);
        float mn = fmaxf(m, mo);
        float c1 = (m  == mn) ? 1.f : __expf(m  - mn);
        float c2 = (mo == mn) ? 1.f : __expf(mo - mn);
        s  = s * c1 + so * c2;
        a0 = a0 * c1 + a0o * c2;
        a1 = a1 * c1 + a1o * c2;
        m  = mn;
    }
    if (lane == 0) {
        out[w * 2 + 0] = a0 / s + b2[0];
        out[w * 2 + 1] = a1 / s + b2[1];
    }
}

// ---------------- launch ----------------
extern "C" void kernel_launch(void* const* d_in, const int* in_sizes, int n_in,
                              void* d_out, int out_size) {
    const float* x   = (const float*)d_in[0];
    const void*  ei  = d_in[1];
    const float* W1  = (const float*)d_in[2];
    const float* as1 = (const float*)d_in[3];
    const float* ad1 = (const float*)d_in[4];
    const float* b1  = (const float*)d_in[5];
    const float* W2  = (const float*)d_in[6];
    const float* as2 = (const float*)d_in[7];
    const float* ad2 = (const float*)d_in[8];
    const float* b2  = (const float*)d_in[9];

    int n = in_sizes[0] / 256;
    int e = in_sizes[1] / 2;

    int warpBlocks = (n * 32 + 255) / 256;

    k_init<<<(n + 255) / 256, 256>>>((const int*)ei, n);

    dim3 gg((n + 127) / 128, 2);
    k_gemm1<<<gg, 256>>>(x, W1, n);
    k_alpha1<<<warpBlocks, 256>>>(as1, ad1, n);

    k_hist<<<(e + 255) / 256, 256>>>(ei, e);
    k_scan<<<1, 1024>>>(n);
    k_scatter<<<(e + n + 255) / 256, 256>>>(ei, e, n);

    k_agg1<<<warpBlocks, 256>>>(b1, n);
    k_gemm2a<<<warpBlocks, 256>>>(W2, as2, ad2, n);
    k_agg2<<<warpBlocks, 256>>>(b2, (float*)d_out, n);
}

// round 4
// speedup vs baseline: 1.9818x; 1.2297x over previous
#include <cuda_runtime.h>
#include <cuda_fp16.h>
#include <math.h>
#include <stdint.h>

#define NMAX 50000
#define EMAX 800000
#define TOT_E (EMAX + NMAX)

// ---------------- scratch ----------------
__device__ __half g_xph[NMAX * 256];
__device__ float  g_asrc[NMAX * 8];
__device__ float  g_adst[NMAX * 8];
__device__ int    g_deg[NMAX];
__device__ int    g_rowstart[NMAX + 1];
__device__ int    g_cursor[NMAX];
__device__ int    g_csr[TOT_E];
__device__ float  g_hp[NMAX * 2];
__device__ float  g_as2[NMAX];
__device__ float  g_ad2[NMAX];
__device__ int    g_is64;

// ---------------- mma helpers ----------------
__device__ __forceinline__ uint32_t sptr(const void* p) {
    return (uint32_t)__cvta_generic_to_shared(p);
}
__device__ __forceinline__ void ldsm4(uint32_t* r, uint32_t a) {
    asm volatile("ldmatrix.sync.aligned.m8n8.x4.shared.b16 {%0,%1,%2,%3},[%4];"
        : "=r"(r[0]), "=r"(r[1]), "=r"(r[2]), "=r"(r[3]) : "r"(a));
}
__device__ __forceinline__ void ldsm4t(uint32_t* r, uint32_t a) {
    asm volatile("ldmatrix.sync.aligned.m8n8.x4.trans.shared.b16 {%0,%1,%2,%3},[%4];"
        : "=r"(r[0]), "=r"(r[1]), "=r"(r[2]), "=r"(r[3]) : "r"(a));
}
__device__ __forceinline__ void mma16816(float* c, const uint32_t* a, uint32_t b0, uint32_t b1) {
    asm volatile(
        "mma.sync.aligned.m16n8k16.row.col.f32.f16.f16.f32 "
        "{%0,%1,%2,%3},{%4,%5,%6,%7},{%8,%9},{%0,%1,%2,%3};"
        : "+f"(c[0]), "+f"(c[1]), "+f"(c[2]), "+f"(c[3])
        : "r"(a[0]), "r"(a[1]), "r"(a[2]), "r"(a[3]), "r"(b0), "r"(b1));
}

__device__ __forceinline__ int load_idx(const void* ei, int i, int is64) {
    if (is64) return (int)((const long long*)ei)[i];
    return ((const int*)ei)[i];
}

// ---------------- init: zero counters + parallel dtype detect ----------------
__global__ void k_init(const int* __restrict__ ei32, int n) {
    int t = blockIdx.x * blockDim.x + threadIdx.x;
    if (t < n) { g_deg[t] = 0; g_cursor[t] = 0; }
    if (blockIdx.x == 0 && threadIdx.x < 32) {
        int bad = 0;
        #pragma unroll
        for (int i = threadIdx.x; i < 64; i += 32)
            bad |= (ei32[2 * i + 1] != 0);
        unsigned m = __ballot_sync(0xffffffffu, bad);
        if (threadIdx.x == 0) g_is64 = (m == 0);
    }
}

// ---------------- layer-1 GEMM + fused attention logits ----------------
// xp(fp16) = fp16(x) @ fp16(W1); alpha_src/alpha_dst computed in epilogue.
// 128x128x32 tiles, 256 threads (8 warps as 4x2), warp tile 32x64.
// Column block y owns heads [4y, 4y+4) exclusively.
__global__ void __launch_bounds__(256, 2) k_gemm1(const float* __restrict__ X,
                                                  const float* __restrict__ W,
                                                  const float* __restrict__ As1,
                                                  const float* __restrict__ Ad1, int M) {
    const int BM = 128;
    __shared__ __half As[BM][40];
    __shared__ __half Bs[32][136];
    __shared__ float  sA[128][4];
    __shared__ float  sD[128][4];
    int t    = threadIdx.x;
    int wid  = t >> 5, lane = t & 31;
    int lr   = lane & 7, lg = lane >> 3;
    int wm   = (wid >> 1) * 32;
    int wn   = (wid & 1) * 64;
    int rowBase = blockIdx.x * BM;
    int colBase = blockIdx.y * BM;
    int hb      = blockIdx.y * 4;

    // zero alpha accumulators (visible by first __syncthreads below)
    #pragma unroll
    for (int i = t; i < 512; i += 256) {
        ((float*)sA)[i] = 0.f;
        ((float*)sD)[i] = 0.f;
    }

    float c[2][8][4];
    #pragma unroll
    for (int i = 0; i < 2; i++)
        #pragma unroll
        for (int j = 0; j < 8; j++)
            #pragma unroll
            for (int k = 0; k < 4; k++) c[i][j][k] = 0.f;

    float4 ra[4], rb[4];
    // initial tile loads (kt=0)
    #pragma unroll
    for (int i = 0; i < 4; i++) {
        int q = t + i * 256;
        int r = q >> 3, kq = (q & 7) * 4;
        int grow = rowBase + r;
        ra[i] = (grow < M) ? *(const float4*)(X + (size_t)grow * 256 + kq)
                           : make_float4(0.f, 0.f, 0.f, 0.f);
    }
    #pragma unroll
    for (int i = 0; i < 4; i++) {
        int q = t + i * 256;
        int r = q >> 5, c4 = (q & 31) * 4;
        rb[i] = *(const float4*)(W + (size_t)r * 256 + colBase + c4);
    }
    #pragma unroll
    for (int i = 0; i < 4; i++) {
        int q = t + i * 256;
        int r = q >> 3, kq = (q & 7) * 4;
        *(__half2*)&As[r][kq]     = __floats2half2_rn(ra[i].x, ra[i].y);
        *(__half2*)&As[r][kq + 2] = __floats2half2_rn(ra[i].z, ra[i].w);
    }
    #pragma unroll
    for (int i = 0; i < 4; i++) {
        int q = t + i * 256;
        int r = q >> 5, c4 = (q & 31) * 4;
        *(__half2*)&Bs[r][c4]     = __floats2half2_rn(rb[i].x, rb[i].y);
        *(__half2*)&Bs[r][c4 + 2] = __floats2half2_rn(rb[i].z, rb[i].w);
    }
    __syncthreads();

    for (int kt = 0; kt < 256; kt += 32) {
        bool more = (kt + 32) < 256;
        if (more) {
            // prefetch next tile into regs (overlaps with MMAs below)
            #pragma unroll
            for (int i = 0; i < 4; i++) {
                int q = t + i * 256;
                int r = q >> 3, kq = (q & 7) * 4;
                int grow = rowBase + r;
                ra[i] = (grow < M) ? *(const float4*)(X + (size_t)grow * 256 + kt + 32 + kq)
                                   : make_float4(0.f, 0.f, 0.f, 0.f);
            }
            #pragma unroll
            for (int i = 0; i < 4; i++) {
                int q = t + i * 256;
                int r = q >> 5, c4 = (q & 31) * 4;
                rb[i] = *(const float4*)(W + (size_t)(kt + 32 + r) * 256 + colBase + c4);
            }
        }
        #pragma unroll
        for (int ks = 0; ks < 2; ks++) {
            uint32_t a[2][4], b[4][4];
            #pragma unroll
            for (int mt = 0; mt < 2; mt++) {
                int row = wm + mt * 16 + lr + (lg & 1) * 8;
                int col = ks * 16 + (lg >> 1) * 8;
                ldsm4(a[mt], sptr(&As[row][col]));
            }
            #pragma unroll
            for (int ng = 0; ng < 4; ng++) {
                int krow = ks * 16 + lr + (lg & 1) * 8;
                int col  = wn + ng * 16 + (lg >> 1) * 8;
                ldsm4t(b[ng], sptr(&Bs[krow][col]));
            }
            #pragma unroll
            for (int mt = 0; mt < 2; mt++)
                #pragma unroll
                for (int nt = 0; nt < 8; nt++)
                    mma16816(c[mt][nt], a[mt], b[nt >> 1][(nt & 1) * 2],
                             b[nt >> 1][(nt & 1) * 2 + 1]);
        }
        if (more) {
            __syncthreads();
            #pragma unroll
            for (int i = 0; i < 4; i++) {
                int q = t + i * 256;
                int r = q >> 3, kq = (q & 7) * 4;
                *(__half2*)&As[r][kq]     = __floats2half2_rn(ra[i].x, ra[i].y);
                *(__half2*)&As[r][kq + 2] = __floats2half2_rn(ra[i].z, ra[i].w);
            }
            #pragma unroll
            for (int i = 0; i < 4; i++) {
                int q = t + i * 256;
                int r = q >> 5, c4 = (q & 31) * 4;
                *(__half2*)&Bs[r][c4]     = __floats2half2_rn(rb[i].x, rb[i].y);
                *(__half2*)&Bs[r][c4 + 2] = __floats2half2_rn(rb[i].z, rb[i].w);
            }
            __syncthreads();
        }
    }

    // epilogue 1: store xp fp16
    #pragma unroll
    for (int mt = 0; mt < 2; mt++) {
        int r0 = rowBase + wm + mt * 16 + (lane >> 2);
        #pragma unroll
        for (int nt = 0; nt < 8; nt++) {
            int col = colBase + wn + nt * 8 + (lane & 3) * 2;
            if (r0 < M)
                *(__half2*)(g_xph + (size_t)r0 * 256 + col) =
                    __floats2half2_rn(c[mt][nt][0], c[mt][nt][1]);
            if (r0 + 8 < M)
                *(__half2*)(g_xph + (size_t)(r0 + 8) * 256 + col) =
                    __floats2half2_rn(c[mt][nt][2], c[mt][nt][3]);
        }
    }

    // epilogue 2: attention logit partials -> smem
    float asw[16], adw[16];
    #pragma unroll
    for (int nt = 0; nt < 8; nt++)
        #pragma unroll
        for (int b = 0; b < 2; b++) {
            int col = wn + nt * 8 + (lane & 3) * 2 + b;
            asw[nt * 2 + b] = As1[colBase + col];
            adw[nt * 2 + b] = Ad1[colBase + col];
        }
    int h0 = wn >> 5, h1 = h0 + 1;
    #pragma unroll
    for (int mt = 0; mt < 2; mt++)
        #pragma unroll
        for (int hf = 0; hf < 2; hf++) {
            int rl = wm + mt * 16 + (lane >> 2) + 8 * hf;
            float s0 = 0.f, s1 = 0.f, d0 = 0.f, d1 = 0.f;
            #pragma unroll
            for (int nt = 0; nt < 8; nt++) {
                float v0 = c[mt][nt][hf * 2 + 0];
                float v1 = c[mt][nt][hf * 2 + 1];
                float cs = v0 * asw[nt * 2] + v1 * asw[nt * 2 + 1];
                float cd = v0 * adw[nt * 2] + v1 * adw[nt * 2 + 1];
                if (nt < 4) { s0 += cs; d0 += cd; }
                else        { s1 += cs; d1 += cd; }
            }
            atomicAdd(&sA[rl][h0], s0);
            atomicAdd(&sA[rl][h1], s1);
            atomicAdd(&sD[rl][h0], d0);
            atomicAdd(&sD[rl][h1], d1);
        }
    __syncthreads();
    #pragma unroll
    for (int i = t; i < 512; i += 256) {
        int r = i >> 2, hl = i & 3;
        int grow = rowBase + r;
        if (grow < M) {
            g_asrc[grow * 8 + hb + hl] = sA[r][hl];
            g_adst[grow * 8 + hb + hl] = sD[r][hl];
        }
    }
}

// ---------------- CSR build ----------------
__global__ void k_hist(const void* __restrict__ ei, int e) {
    int t = blockIdx.x * blockDim.x + threadIdx.x;
    int is64 = g_is64;
    int base = 2 * t;
    if (base + 1 < e) {
        int d0, d1;
        if (is64) {
            longlong2 v = ((const longlong2*)ei)[(e >> 1) + t];   // e even
            d0 = (int)v.x; d1 = (int)v.y;
        } else {
            int2 v = ((const int2*)ei)[(e >> 1) + t];
            d0 = v.x; d1 = v.y;
        }
        atomicAdd(&g_deg[d0], 1);
        atomicAdd(&g_deg[d1], 1);
    } else if (base < e) {
        int d = load_idx(ei, e + base, is64);
        atomicAdd(&g_deg[d], 1);
    }
}

__global__ void k_scan(int n) {
    __shared__ int sums[1024];
    int tid = threadIdx.x;
    int chunk = (n + 1023) / 1024;
    int start = min(tid * chunk, n);
    int end   = min(start + chunk, n);
    int s = 0;
    for (int i = start; i < end; i++) s += g_deg[i] + 1;
    sums[tid] = s;
    __syncthreads();
    for (int off = 1; off < 1024; off <<= 1) {
        int v = (tid >= off) ? sums[tid - off] : 0;
        __syncthreads();
        sums[tid] += v;
        __syncthreads();
    }
    int run = (tid > 0) ? sums[tid - 1] : 0;
    for (int i = start; i < end; i++) {
        g_rowstart[i] = run;
        run += g_deg[i] + 1;
    }
    if (tid == 0) g_rowstart[n] = sums[1023];
}

__global__ void k_scatter(const void* __restrict__ ei, int e, int n) {
    int t = blockIdx.x * blockDim.x + threadIdx.x;
    int ep = e >> 1;
    int is64 = g_is64;
    if (t < ep) {
        int s0, s1, d0, d1;
        if (is64) {
            longlong2 vs = ((const longlong2*)ei)[t];
            longlong2 vd = ((const longlong2*)ei)[ep + t];
            s0 = (int)vs.x; s1 = (int)vs.y; d0 = (int)vd.x; d1 = (int)vd.y;
        } else {
            int2 vs = ((const int2*)ei)[t];
            int2 vd = ((const int2*)ei)[ep + t];
            s0 = vs.x; s1 = vs.y; d0 = vd.x; d1 = vd.y;
        }
        int p0 = atomicAdd(&g_cursor[d0], 1);
        g_csr[g_rowstart[d0] + p0] = s0;
        int p1 = atomicAdd(&g_cursor[d1], 1);
        g_csr[g_rowstart[d1] + p1] = s1;
    } else if ((e & 1) && t == ep) {
        int src = load_idx(ei, e - 1, is64);
        int dst = load_idx(ei, 2 * e - 1, is64);
        int p = atomicAdd(&g_cursor[dst], 1);
        g_csr[g_rowstart[dst] + p] = src;
    } else {
        int node = t - ep - (e & 1);
        if (node < n) {
            int p = atomicAdd(&g_cursor[node], 1);
            g_csr[g_rowstart[node] + p] = node;
        }
    }
}

// ---------------- layer-1 aggregation + fused layer-2 projection ----------------
// No max-subtraction (logits are small; exp safe in fp32).
__global__ void k_agg1(const float* __restrict__ b1, const float* __restrict__ W2,
                       const float* __restrict__ as2w, const float* __restrict__ ad2w, int n) {
    int w    = (blockIdx.x * blockDim.x + threadIdx.x) >> 5;
    int lane = threadIdx.x & 31;
    if (w >= n) return;
    int row = g_rowstart[w], end = g_rowstart[w + 1];
    float adl = (lane < 8) ? g_adst[w * 8 + lane] : 0.f;
    int hidx[4];
    #pragma unroll
    for (int i = 0; i < 4; i++) hidx[i] = 2 * i + (lane >> 4);

    float s = 0.f;
    float2 acc[4] = {{0.f,0.f},{0.f,0.f},{0.f,0.f},{0.f,0.f}};

    int j = row;
    for (; j + 1 < end; j += 2) {
        int sa = g_csr[j], sb = g_csr[j + 1];
        const __half2* xa = (const __half2*)(g_xph + (size_t)sa * 256);
        const __half2* xb = (const __half2*)(g_xph + (size_t)sb * 256);
        __half2 va[4], vb[4];
        #pragma unroll
        for (int i = 0; i < 4; i++) { va[i] = xa[lane + i * 32]; vb[i] = xb[lane + i * 32]; }
        float pa = 0.f, pb = 0.f;
        if (lane < 8) {
            float ea = g_asrc[sa * 8 + lane] + adl;
            float eb = g_asrc[sb * 8 + lane] + adl;
            ea = fmaxf(ea, 0.2f * ea);
            eb = fmaxf(eb, 0.2f * eb);
            pa = __expf(ea);
            pb = __expf(eb);
            s += pa + pb;
        }
        #pragma unroll
        for (int i = 0; i < 4; i++) {
            float pha = __shfl_sync(0xffffffffu, pa, hidx[i]);
            float phb = __shfl_sync(0xffffffffu, pb, hidx[i]);
            float2 fa = __half22float2(va[i]);
            float2 fb = __half22float2(vb[i]);
            acc[i].x = fmaf(fa.x, pha, fmaf(fb.x, phb, acc[i].x));
            acc[i].y = fmaf(fa.y, pha, fmaf(fb.y, phb, acc[i].y));
        }
    }
    if (j < end) {
        int sa = g_csr[j];
        const __half2* xa = (const __half2*)(g_xph + (size_t)sa * 256);
        __half2 va[4];
        #pragma unroll
        for (int i = 0; i < 4; i++) va[i] = xa[lane + i * 32];
        float pa = 0.f;
        if (lane < 8) {
            float ea = g_asrc[sa * 8 + lane] + adl;
            ea = fmaxf(ea, 0.2f * ea);
            pa = __expf(ea);
            s += pa;
        }
        #pragma unroll
        for (int i = 0; i < 4; i++) {
            float pha = __shfl_sync(0xffffffffu, pa, hidx[i]);
            float2 fa = __half22float2(va[i]);
            acc[i].x = fmaf(fa.x, pha, acc[i].x);
            acc[i].y = fmaf(fa.y, pha, acc[i].y);
        }
    }

    // epilogue: h = relu(acc/s + b1) in regs; project to (o0,o1) with W2
    float o0 = 0.f, o1 = 0.f;
    #pragma unroll
    for (int i = 0; i < 4; i++) {
        float sh = __shfl_sync(0xffffffffu, s, hidx[i]);
        int cidx = lane + i * 32;
        float2 bb = *(const float2*)(b1 + 2 * cidx);
        float hx = fmaxf(acc[i].x / sh + bb.x, 0.f);
        float hy = fmaxf(acc[i].y / sh + bb.y, 0.f);
        float4 w4 = *(const float4*)(W2 + 4 * cidx);
        o0 += hx * w4.x + hy * w4.z;
        o1 += hx * w4.y + hy * w4.w;
    }
    #pragma unroll
    for (int off = 16; off; off >>= 1) {
        o0 += __shfl_xor_sync(0xffffffffu, o0, off);
        o1 += __shfl_xor_sync(0xffffffffu, o1, off);
    }
    if (lane == 0) {
        g_hp[w * 2 + 0] = o0;
        g_hp[w * 2 + 1] = o1;
        g_as2[w] = o0 * as2w[0] + o1 * as2w[1];
        g_ad2[w] = o0 * ad2w[0] + o1 * ad2w[1];
    }
}

// ---------------- layer-2 aggregation (no max) ----------------
__global__ void k_agg2(const float* __restrict__ b2, float* __restrict__ out, int n) {
    int w    = (blockIdx.x * blockDim.x + threadIdx.x) >> 5;
    int lane = threadIdx.x & 31;
    if (w >= n) return;
    int row = g_rowstart[w], end = g_rowstart[w + 1];
    float adn = g_ad2[w];

    float s = 0.f, a0 = 0.f, a1 = 0.f;
    for (int j = row + lane; j < end; j += 32) {
        int src = g_csr[j];
        float e = g_as2[src] + adn;
        e = fmaxf(e, 0.2f * e);
        float p = __expf(e);
        float2 hp = *(const float2*)(g_hp + 2 * src);
        s  += p;
        a0 = fmaf(hp.x, p, a0);
        a1 = fmaf(hp.y, p, a1);
    }
    #pragma unroll
    for (int off = 16; off; off >>= 1) {
        s  += __shfl_xor_sync(0xffffffffu, s,  off);
        a0 += __shfl_xor_sync(0xffffffffu, a0, off);
        a1 += __shfl_xor_sync(0xffffffffu, a1, off);
    }
    if (lane == 0) {
        out[w * 2 + 0] = a0 / s + b2[0];
        out[w * 2 + 1] = a1 / s + b2[1];
    }
}

// ---------------- launch ----------------
extern "C" void kernel_launch(void* const* d_in, const int* in_sizes, int n_in,
                              void* d_out, int out_size) {
    const float* x   = (const float*)d_in[0];
    const void*  ei  = d_in[1];
    const float* W1  = (const float*)d_in[2];
    const float* as1 = (const float*)d_in[3];
    const float* ad1 = (const float*)d_in[4];
    const float* b1  = (const float*)d_in[5];
    const float* W2  = (const float*)d_in[6];
    const float* as2 = (const float*)d_in[7];
    const float* ad2 = (const float*)d_in[8];
    const float* b2  = (const float*)d_in[9];

    int n = in_sizes[0] / 256;
    int e = in_sizes[1] / 2;

    int warpBlocks = (n * 32 + 255) / 256;

    k_init<<<(n + 255) / 256, 256>>>((const int*)ei, n);

    dim3 gg((n + 127) / 128, 2);
    k_gemm1<<<gg, 256>>>(x, W1, as1, ad1, n);

    k_hist<<<((e >> 1) + 256) / 256, 256>>>(ei, e);
    k_scan<<<1, 1024>>>(n);
    int scatterThreads = (e >> 1) + (e & 1) + n;
    k_scatter<<<(scatterThreads + 255) / 256, 256>>>(ei, e, n);

    k_agg1<<<warpBlocks, 256>>>(b1, W2, as2, ad2, n);
    k_agg2<<<warpBlocks, 256>>>(b2, (float*)d_out, n);
}

// round 5
// speedup vs baseline: 2.7548x; 1.3900x over previous
#include <cuda_runtime.h>
#include <cuda_fp16.h>
#include <math.h>
#include <stdint.h>

#define NMAX 50000
#define EMAX 800000
#define TOT_E (EMAX + NMAX)

// ---------------- scratch ----------------
__device__ __half g_xph[NMAX * 256];
__device__ float  g_asrc[NMAX * 8];
__device__ float  g_adst[NMAX * 8];
__device__ int    g_deg[NMAX];
__device__ int    g_rowstart[NMAX + 1];
__device__ int    g_cursor[NMAX];
__device__ int    g_csr[TOT_E];
__device__ float  g_hp[NMAX * 2];
__device__ float  g_as2[NMAX];
__device__ float  g_ad2[NMAX];
__device__ int    g_is64;
__device__ int    g_bsum[256];
__device__ int    g_boff[256];

// ---------------- mma helpers ----------------
__device__ __forceinline__ uint32_t sptr(const void* p) {
    return (uint32_t)__cvta_generic_to_shared(p);
}
__device__ __forceinline__ void ldsm4(uint32_t* r, uint32_t a) {
    asm volatile("ldmatrix.sync.aligned.m8n8.x4.shared.b16 {%0,%1,%2,%3},[%4];"
        : "=r"(r[0]), "=r"(r[1]), "=r"(r[2]), "=r"(r[3]) : "r"(a));
}
__device__ __forceinline__ void ldsm4t(uint32_t* r, uint32_t a) {
    asm volatile("ldmatrix.sync.aligned.m8n8.x4.trans.shared.b16 {%0,%1,%2,%3},[%4];"
        : "=r"(r[0]), "=r"(r[1]), "=r"(r[2]), "=r"(r[3]) : "r"(a));
}
__device__ __forceinline__ void mma16816(float* c, const uint32_t* a, uint32_t b0, uint32_t b1) {
    asm volatile(
        "mma.sync.aligned.m16n8k16.row.col.f32.f16.f16.f32 "
        "{%0,%1,%2,%3},{%4,%5,%6,%7},{%8,%9},{%0,%1,%2,%3};"
        : "+f"(c[0]), "+f"(c[1]), "+f"(c[2]), "+f"(c[3])
        : "r"(a[0]), "r"(a[1]), "r"(a[2]), "r"(a[3]), "r"(b0), "r"(b1));
}

__device__ __forceinline__ int load_idx(const void* ei, int i, int is64) {
    if (is64) return (int)((const long long*)ei)[i];
    return ((const int*)ei)[i];
}

// ---------------- init: zero counters + parallel dtype detect ----------------
__global__ void k_init(const int* __restrict__ ei32, int n) {
    int t = blockIdx.x * blockDim.x + threadIdx.x;
    if (t < n) { g_deg[t] = 0; g_cursor[t] = 0; }
    if (blockIdx.x == 0 && threadIdx.x < 32) {
        int bad = 0;
        #pragma unroll
        for (int i = threadIdx.x; i < 64; i += 32)
            bad |= (ei32[2 * i + 1] != 0);
        unsigned m = __ballot_sync(0xffffffffu, bad);
        if (threadIdx.x == 0) g_is64 = (m == 0);
    }
}

// ---------------- layer-1 GEMM + fused attention logits ----------------
__global__ void __launch_bounds__(256, 2) k_gemm1(const float* __restrict__ X,
                                                  const float* __restrict__ W,
                                                  const float* __restrict__ As1,
                                                  const float* __restrict__ Ad1, int M) {
    const int BM = 128;
    __shared__ __half As[BM][40];
    __shared__ __half Bs[32][136];
    __shared__ float  sA[128][4];
    __shared__ float  sD[128][4];
    int t    = threadIdx.x;
    int wid  = t >> 5, lane = t & 31;
    int lr   = lane & 7, lg = lane >> 3;
    int wm   = (wid >> 1) * 32;
    int wn   = (wid & 1) * 64;
    int rowBase = blockIdx.x * BM;
    int colBase = blockIdx.y * BM;
    int hb      = blockIdx.y * 4;

    #pragma unroll
    for (int i = t; i < 512; i += 256) {
        ((float*)sA)[i] = 0.f;
        ((float*)sD)[i] = 0.f;
    }

    float c[2][8][4];
    #pragma unroll
    for (int i = 0; i < 2; i++)
        #pragma unroll
        for (int j = 0; j < 8; j++)
            #pragma unroll
            for (int k = 0; k < 4; k++) c[i][j][k] = 0.f;

    float4 ra[4], rb[4];
    #pragma unroll
    for (int i = 0; i < 4; i++) {
        int q = t + i * 256;
        int r = q >> 3, kq = (q & 7) * 4;
        int grow = rowBase + r;
        ra[i] = (grow < M) ? *(const float4*)(X + (size_t)grow * 256 + kq)
                           : make_float4(0.f, 0.f, 0.f, 0.f);
    }
    #pragma unroll
    for (int i = 0; i < 4; i++) {
        int q = t + i * 256;
        int r = q >> 5, c4 = (q & 31) * 4;
        rb[i] = *(const float4*)(W + (size_t)r * 256 + colBase + c4);
    }
    #pragma unroll
    for (int i = 0; i < 4; i++) {
        int q = t + i * 256;
        int r = q >> 3, kq = (q & 7) * 4;
        *(__half2*)&As[r][kq]     = __floats2half2_rn(ra[i].x, ra[i].y);
        *(__half2*)&As[r][kq + 2] = __floats2half2_rn(ra[i].z, ra[i].w);
    }
    #pragma unroll
    for (int i = 0; i < 4; i++) {
        int q = t + i * 256;
        int r = q >> 5, c4 = (q & 31) * 4;
        *(__half2*)&Bs[r][c4]     = __floats2half2_rn(rb[i].x, rb[i].y);
        *(__half2*)&Bs[r][c4 + 2] = __floats2half2_rn(rb[i].z, rb[i].w);
    }
    __syncthreads();

    for (int kt = 0; kt < 256; kt += 32) {
        bool more = (kt + 32) < 256;
        if (more) {
            #pragma unroll
            for (int i = 0; i < 4; i++) {
                int q = t + i * 256;
                int r = q >> 3, kq = (q & 7) * 4;
                int grow = rowBase + r;
                ra[i] = (grow < M) ? *(const float4*)(X + (size_t)grow * 256 + kt + 32 + kq)
                                   : make_float4(0.f, 0.f, 0.f, 0.f);
            }
            #pragma unroll
            for (int i = 0; i < 4; i++) {
                int q = t + i * 256;
                int r = q >> 5, c4 = (q & 31) * 4;
                rb[i] = *(const float4*)(W + (size_t)(kt + 32 + r) * 256 + colBase + c4);
            }
        }
        #pragma unroll
        for (int ks = 0; ks < 2; ks++) {
            uint32_t a[2][4], b[4][4];
            #pragma unroll
            for (int mt = 0; mt < 2; mt++) {
                int row = wm + mt * 16 + lr + (lg & 1) * 8;
                int col = ks * 16 + (lg >> 1) * 8;
                ldsm4(a[mt], sptr(&As[row][col]));
            }
            #pragma unroll
            for (int ng = 0; ng < 4; ng++) {
                int krow = ks * 16 + lr + (lg & 1) * 8;
                int col  = wn + ng * 16 + (lg >> 1) * 8;
                ldsm4t(b[ng], sptr(&Bs[krow][col]));
            }
            #pragma unroll
            for (int mt = 0; mt < 2; mt++)
                #pragma unroll
                for (int nt = 0; nt < 8; nt++)
                    mma16816(c[mt][nt], a[mt], b[nt >> 1][(nt & 1) * 2],
                             b[nt >> 1][(nt & 1) * 2 + 1]);
        }
        if (more) {
            __syncthreads();
            #pragma unroll
            for (int i = 0; i < 4; i++) {
                int q = t + i * 256;
                int r = q >> 3, kq = (q & 7) * 4;
                *(__half2*)&As[r][kq]     = __floats2half2_rn(ra[i].x, ra[i].y);
                *(__half2*)&As[r][kq + 2] = __floats2half2_rn(ra[i].z, ra[i].w);
            }
            #pragma unroll
            for (int i = 0; i < 4; i++) {
                int q = t + i * 256;
                int r = q >> 5, c4 = (q & 31) * 4;
                *(__half2*)&Bs[r][c4]     = __floats2half2_rn(rb[i].x, rb[i].y);
                *(__half2*)&Bs[r][c4 + 2] = __floats2half2_rn(rb[i].z, rb[i].w);
            }
            __syncthreads();
        }
    }

    // epilogue 1: store xp fp16
    #pragma unroll
    for (int mt = 0; mt < 2; mt++) {
        int r0 = rowBase + wm + mt * 16 + (lane >> 2);
        #pragma unroll
        for (int nt = 0; nt < 8; nt++) {
            int col = colBase + wn + nt * 8 + (lane & 3) * 2;
            if (r0 < M)
                *(__half2*)(g_xph + (size_t)r0 * 256 + col) =
                    __floats2half2_rn(c[mt][nt][0], c[mt][nt][1]);
            if (r0 + 8 < M)
                *(__half2*)(g_xph + (size_t)(r0 + 8) * 256 + col) =
                    __floats2half2_rn(c[mt][nt][2], c[mt][nt][3]);
        }
    }

    // epilogue 2: attention logit partials -> smem
    float asw[16], adw[16];
    #pragma unroll
    for (int nt = 0; nt < 8; nt++)
        #pragma unroll
        for (int b = 0; b < 2; b++) {
            int col = wn + nt * 8 + (lane & 3) * 2 + b;
            asw[nt * 2 + b] = As1[colBase + col];
            adw[nt * 2 + b] = Ad1[colBase + col];
        }
    int h0 = wn >> 5, h1 = h0 + 1;
    #pragma unroll
    for (int mt = 0; mt < 2; mt++)
        #pragma unroll
        for (int hf = 0; hf < 2; hf++) {
            int rl = wm + mt * 16 + (lane >> 2) + 8 * hf;
            float s0 = 0.f, s1 = 0.f, d0 = 0.f, d1 = 0.f;
            #pragma unroll
            for (int nt = 0; nt < 8; nt++) {
                float v0 = c[mt][nt][hf * 2 + 0];
                float v1 = c[mt][nt][hf * 2 + 1];
                float cs = v0 * asw[nt * 2] + v1 * asw[nt * 2 + 1];
                float cd = v0 * adw[nt * 2] + v1 * adw[nt * 2 + 1];
                if (nt < 4) { s0 += cs; d0 += cd; }
                else        { s1 += cs; d1 += cd; }
            }
            atomicAdd(&sA[rl][h0], s0);
            atomicAdd(&sA[rl][h1], s1);
            atomicAdd(&sD[rl][h0], d0);
            atomicAdd(&sD[rl][h1], d1);
        }
    __syncthreads();
    #pragma unroll
    for (int i = t; i < 512; i += 256) {
        int r = i >> 2, hl = i & 3;
        int grow = rowBase + r;
        if (grow < M) {
            g_asrc[grow * 8 + hb + hl] = sA[r][hl];
            g_adst[grow * 8 + hb + hl] = sD[r][hl];
        }
    }
}

// ---------------- CSR build ----------------
__global__ void k_hist(const void* __restrict__ ei, int e) {
    int t = blockIdx.x * blockDim.x + threadIdx.x;
    int is64 = g_is64;
    int base = 2 * t;
    if (base + 1 < e) {
        int d0, d1;
        if (is64) {
            longlong2 v = ((const longlong2*)ei)[(e >> 1) + t];
            d0 = (int)v.x; d1 = (int)v.y;
        } else {
            int2 v = ((const int2*)ei)[(e >> 1) + t];
            d0 = v.x; d1 = v.y;
        }
        atomicAdd(&g_deg[d0], 1);
        atomicAdd(&g_deg[d1], 1);
    } else if (base < e) {
        int d = load_idx(ei, e + base, is64);
        atomicAdd(&g_deg[d], 1);
    }
}

// ---------------- parallel 3-phase exclusive scan of (deg+1) ----------------
__global__ void k_scanA(int n) {
    int i = blockIdx.x * 256 + threadIdx.x;
    int lane = threadIdx.x & 31, wid = threadIdx.x >> 5;
    int v = (i < n) ? (g_deg[i] + 1) : 0;
    int x = v;
    #pragma unroll
    for (int o = 1; o < 32; o <<= 1) {
        int y = __shfl_up_sync(0xffffffffu, x, o);
        if (lane >= o) x += y;
    }
    __shared__ int ws[8];
    if (lane == 31) ws[wid] = x;
    __syncthreads();
    if (threadIdx.x < 8) {
        int w = ws[threadIdx.x];
        #pragma unroll
        for (int o = 1; o < 8; o <<= 1) {
            int y = __shfl_up_sync(0xffu, w, o);
            if ((int)threadIdx.x >= o) w += y;
        }
        ws[threadIdx.x] = w;
    }
    __syncthreads();
    int base = (wid ? ws[wid - 1] : 0);
    if (i < n) g_rowstart[i] = base + x - v;      // block-local exclusive
    if (threadIdx.x == 255) g_bsum[blockIdx.x] = ws[7];
}

__global__ void k_scanB(int nb) {
    int t = threadIdx.x;
    int lane = t & 31, wid = t >> 5;
    int v = (t < nb) ? g_bsum[t] : 0;
    int x = v;
    #pragma unroll
    for (int o = 1; o < 32; o <<= 1) {
        int y = __shfl_up_sync(0xffffffffu, x, o);
        if (lane >= o) x += y;
    }
    __shared__ int ws[8];
    if (lane == 31) ws[wid] = x;
    __syncthreads();
    if (t < 8) {
        int w = ws[t];
        #pragma unroll
        for (int o = 1; o < 8; o <<= 1) {
            int y = __shfl_up_sync(0xffu, w, o);
            if (t >= o) w += y;
        }
        ws[t] = w;
    }
    __syncthreads();
    int base = (wid ? ws[wid - 1] : 0);
    g_boff[t] = base + x - v;                     // exclusive block offsets
}

__global__ void k_scanC(int n, int total) {
    int i = blockIdx.x * 256 + threadIdx.x;
    if (i < n) g_rowstart[i] += g_boff[i >> 8];
    if (i == 0) g_rowstart[n] = total;
}

__global__ void k_scatter(const void* __restrict__ ei, int e, int n) {
    int t = blockIdx.x * blockDim.x + threadIdx.x;
    int ep = e >> 1;
    int is64 = g_is64;
    if (t < ep) {
        int s0, s1, d0, d1;
        if (is64) {
            longlong2 vs = ((const longlong2*)ei)[t];
            longlong2 vd = ((const longlong2*)ei)[ep + t];
            s0 = (int)vs.x; s1 = (int)vs.y; d0 = (int)vd.x; d1 = (int)vd.y;
        } else {
            int2 vs = ((const int2*)ei)[t];
            int2 vd = ((const int2*)ei)[ep + t];
            s0 = vs.x; s1 = vs.y; d0 = vd.x; d1 = vd.y;
        }
        int p0 = atomicAdd(&g_cursor[d0], 1);
        g_csr[g_rowstart[d0] + p0] = s0;
        int p1 = atomicAdd(&g_cursor[d1], 1);
        g_csr[g_rowstart[d1] + p1] = s1;
    } else if ((e & 1) && t == ep) {
        int src = load_idx(ei, e - 1, is64);
        int dst = load_idx(ei, 2 * e - 1, is64);
        int p = atomicAdd(&g_cursor[dst], 1);
        g_csr[g_rowstart[dst] + p] = src;
    } else {
        int node = t - ep - (e & 1);
        if (node < n) {
            int p = atomicAdd(&g_cursor[node], 1);
            g_csr[g_rowstart[node] + p] = node;
        }
    }
}

// ---------------- layer-1 aggregation + fused layer-2 projection ----------------
__global__ void k_agg1(const float* __restrict__ b1, const float* __restrict__ W2,
                       const float* __restrict__ as2w, const float* __restrict__ ad2w, int n) {
    int w    = (blockIdx.x * blockDim.x + threadIdx.x) >> 5;
    int lane = threadIdx.x & 31;
    if (w >= n) return;
    int row = g_rowstart[w], end = g_rowstart[w + 1];
    float adl = (lane < 8) ? g_adst[w * 8 + lane] : 0.f;
    int hidx[4];
    #pragma unroll
    for (int i = 0; i < 4; i++) hidx[i] = 2 * i + (lane >> 4);

    float s = 0.f;
    float2 acc[4] = {{0.f,0.f},{0.f,0.f},{0.f,0.f},{0.f,0.f}};

    int j = row;
    for (; j + 1 < end; j += 2) {
        int sa = g_csr[j], sb = g_csr[j + 1];
        const __half2* xa = (const __half2*)(g_xph + (size_t)sa * 256);
        const __half2* xb = (const __half2*)(g_xph + (size_t)sb * 256);
        __half2 va[4], vb[4];
        #pragma unroll
        for (int i = 0; i < 4; i++) { va[i] = xa[lane + i * 32]; vb[i] = xb[lane + i * 32]; }
        float pa = 0.f, pb = 0.f;
        if (lane < 8) {
            float ea = g_asrc[sa * 8 + lane] + adl;
            float eb = g_asrc[sb * 8 + lane] + adl;
            ea = fmaxf(ea, 0.2f * ea);
            eb = fmaxf(eb, 0.2f * eb);
            pa = __expf(ea);
            pb = __expf(eb);
            s += pa + pb;
        }
        #pragma unroll
        for (int i = 0; i < 4; i++) {
            float pha = __shfl_sync(0xffffffffu, pa, hidx[i]);
            float phb = __shfl_sync(0xffffffffu, pb, hidx[i]);
            float2 fa = __half22float2(va[i]);
            float2 fb = __half22float2(vb[i]);
            acc[i].x = fmaf(fa.x, pha, fmaf(fb.x, phb, acc[i].x));
            acc[i].y = fmaf(fa.y, pha, fmaf(fb.y, phb, acc[i].y));
        }
    }
    if (j < end) {
        int sa = g_csr[j];
        const __half2* xa = (const __half2*)(g_xph + (size_t)sa * 256);
        __half2 va[4];
        #pragma unroll
        for (int i = 0; i < 4; i++) va[i] = xa[lane + i * 32];
        float pa = 0.f;
        if (lane < 8) {
            float ea = g_asrc[sa * 8 + lane] + adl;
            ea = fmaxf(ea, 0.2f * ea);
            pa = __expf(ea);
            s += pa;
        }
        #pragma unroll
        for (int i = 0; i < 4; i++) {
            float pha = __shfl_sync(0xffffffffu, pa, hidx[i]);
            float2 fa = __half22float2(va[i]);
            acc[i].x = fmaf(fa.x, pha, acc[i].x);
            acc[i].y = fmaf(fa.y, pha, acc[i].y);
        }
    }

    float o0 = 0.f, o1 = 0.f;
    #pragma unroll
    for (int i = 0; i < 4; i++) {
        float sh = __shfl_sync(0xffffffffu, s, hidx[i]);
        int cidx = lane + i * 32;
        float2 bb = *(const float2*)(b1 + 2 * cidx);
        float hx = fmaxf(acc[i].x / sh + bb.x, 0.f);
        float hy = fmaxf(acc[i].y / sh + bb.y, 0.f);
        float4 w4 = *(const float4*)(W2 + 4 * cidx);
        o0 += hx * w4.x + hy * w4.z;
        o1 += hx * w4.y + hy * w4.w;
    }
    #pragma unroll
    for (int off = 16; off; off >>= 1) {
        o0 += __shfl_xor_sync(0xffffffffu, o0, off);
        o1 += __shfl_xor_sync(0xffffffffu, o1, off);
    }
    if (lane == 0) {
        g_hp[w * 2 + 0] = o0;
        g_hp[w * 2 + 1] = o1;
        g_as2[w] = o0 * as2w[0] + o1 * as2w[1];
        g_ad2[w] = o0 * ad2w[0] + o1 * ad2w[1];
    }
}

// ---------------- layer-2 aggregation ----------------
__global__ void k_agg2(const float* __restrict__ b2, float* __restrict__ out, int n) {
    int w    = (blockIdx.x * blockDim.x + threadIdx.x) >> 5;
    int lane = threadIdx.x & 31;
    if (w >= n) return;
    int row = g_rowstart[w], end = g_rowstart[w + 1];
    float adn = g_ad2[w];

    float s = 0.f, a0 = 0.f, a1 = 0.f;
    for (int j = row + lane; j < end; j += 32) {
        int src = g_csr[j];
        float e = g_as2[src] + adn;
        e = fmaxf(e, 0.2f * e);
        float p = __expf(e);
        float2 hp = *(const float2*)(g_hp + 2 * src);
        s  += p;
        a0 = fmaf(hp.x, p, a0);
        a1 = fmaf(hp.y, p, a1);
    }
    #pragma unroll
    for (int off = 16; off; off >>= 1) {
        s  += __shfl_xor_sync(0xffffffffu, s,  off);
        a0 += __shfl_xor_sync(0xffffffffu, a0, off);
        a1 += __shfl_xor_sync(0xffffffffu, a1, off);
    }
    if (lane == 0) {
        out[w * 2 + 0] = a0 / s + b2[0];
        out[w * 2 + 1] = a1 / s + b2[1];
    }
}

// ---------------- launch ----------------
extern "C" void kernel_launch(void* const* d_in, const int* in_sizes, int n_in,
                              void* d_out, int out_size) {
    const float* x   = (const float*)d_in[0];
    const void*  ei  = d_in[1];
    const float* W1  = (const float*)d_in[2];
    const float* as1 = (const float*)d_in[3];
    const float* ad1 = (const float*)d_in[4];
    const float* b1  = (const float*)d_in[5];
    const float* W2  = (const float*)d_in[6];
    const float* as2 = (const float*)d_in[7];
    const float* ad2 = (const float*)d_in[8];
    const float* b2  = (const float*)d_in[9];

    int n = in_sizes[0] / 256;
    int e = in_sizes[1] / 2;

    int warpBlocks = (n * 32 + 255) / 256;
    int nb = (n + 255) / 256;

    // one-time stream/event setup (host objects only; created on the
    // correctness call, reused during graph capture)
    static cudaStream_t s1 = 0, s2 = 0;
    static cudaEvent_t ev0 = 0, ev1 = 0, ev2 = 0;
    if (!s1) {
        cudaStreamCreateWithFlags(&s1, cudaStreamNonBlocking);
        cudaStreamCreateWithFlags(&s2, cudaStreamNonBlocking);
        cudaEventCreateWithFlags(&ev0, cudaEventDisableTiming);
        cudaEventCreateWithFlags(&ev1, cudaEventDisableTiming);
        cudaEventCreateWithFlags(&ev2, cudaEventDisableTiming);
    }

    // fork
    cudaEventRecord(ev0, 0);
    cudaStreamWaitEvent(s1, ev0, 0);
    cudaStreamWaitEvent(s2, ev0, 0);

    // branch A: GEMM + fused logits
    dim3 gg((n + 127) / 128, 2);
    k_gemm1<<<gg, 256, 0, s1>>>(x, W1, as1, ad1, n);

    // branch B: CSR build
    k_init<<<(n + 255) / 256, 256, 0, s2>>>((const int*)ei, n);
    k_hist<<<((e >> 1) + 256) / 256, 256, 0, s2>>>(ei, e);
    k_scanA<<<nb, 256, 0, s2>>>(n);
    k_scanB<<<1, 256, 0, s2>>>(nb);
    k_scanC<<<nb, 256, 0, s2>>>(n, e + n);
    int scatterThreads = (e >> 1) + (e & 1) + n;
    k_scatter<<<(scatterThreads + 255) / 256, 256, 0, s2>>>(ei, e, n);

    // join
    cudaEventRecord(ev1, s1);
    cudaEventRecord(ev2, s2);
    cudaStreamWaitEvent(0, ev1, 0);
    cudaStreamWaitEvent(0, ev2, 0);

    k_agg1<<<warpBlocks, 256>>>(b1, W2, as2, ad2, n);
    k_agg2<<<warpBlocks, 256>>>(b2, (float*)d_out, n);
}

// round 6
// speedup vs baseline: 2.9262x; 1.0622x over previous
#include <cuda_runtime.h>
#include <cuda_fp16.h>
#include <math.h>
#include <stdint.h>

#define NMAX 50000
#define EMAX 800000
#define TOT_E (EMAX + NMAX)

// ---------------- scratch ----------------
__device__ __half g_xph[NMAX * 256];
__device__ float  g_asrc[NMAX * 8];
__device__ float  g_adst[NMAX * 8];
__device__ int    g_deg[NMAX];
__device__ int    g_rowstart[NMAX + 1];
__device__ int    g_cursor[NMAX];
__device__ int    g_csr[TOT_E];
__device__ float  g_hp[NMAX * 2];
__device__ float  g_as2[NMAX];
__device__ float  g_ad2[NMAX];
__device__ int    g_is64;
__device__ int    g_bsum[256];
__device__ int    g_boff[256];

// ---------------- mma helpers ----------------
__device__ __forceinline__ uint32_t sptr(const void* p) {
    return (uint32_t)__cvta_generic_to_shared(p);
}
__device__ __forceinline__ void ldsm4(uint32_t* r, uint32_t a) {
    asm volatile("ldmatrix.sync.aligned.m8n8.x4.shared.b16 {%0,%1,%2,%3},[%4];"
        : "=r"(r[0]), "=r"(r[1]), "=r"(r[2]), "=r"(r[3]) : "r"(a));
}
__device__ __forceinline__ void ldsm4t(uint32_t* r, uint32_t a) {
    asm volatile("ldmatrix.sync.aligned.m8n8.x4.trans.shared.b16 {%0,%1,%2,%3},[%4];"
        : "=r"(r[0]), "=r"(r[1]), "=r"(r[2]), "=r"(r[3]) : "r"(a));
}
__device__ __forceinline__ void mma16816(float* c, const uint32_t* a, uint32_t b0, uint32_t b1) {
    asm volatile(
        "mma.sync.aligned.m16n8k16.row.col.f32.f16.f16.f32 "
        "{%0,%1,%2,%3},{%4,%5,%6,%7},{%8,%9},{%0,%1,%2,%3};"
        : "+f"(c[0]), "+f"(c[1]), "+f"(c[2]), "+f"(c[3])
        : "r"(a[0]), "r"(a[1]), "r"(a[2]), "r"(a[3]), "r"(b0), "r"(b1));
}

__device__ __forceinline__ int load_idx(const void* ei, int i, int is64) {
    if (is64) return (int)((const long long*)ei)[i];
    return ((const int*)ei)[i];
}

// ---------------- init ----------------
__global__ void k_init(const int* __restrict__ ei32, int n) {
    int t = blockIdx.x * blockDim.x + threadIdx.x;
    if (t < n) { g_deg[t] = 0; g_cursor[t] = 0; }
    if (blockIdx.x == 0 && threadIdx.x < 32) {
        int bad = 0;
        #pragma unroll
        for (int i = threadIdx.x; i < 64; i += 32)
            bad |= (ei32[2 * i + 1] != 0);
        unsigned m = __ballot_sync(0xffffffffu, bad);
        if (threadIdx.x == 0) g_is64 = (m == 0);
    }
}

// ---------------- layer-1 GEMM + fused attention logits (double-buffered) ----------------
__global__ void __launch_bounds__(256, 2) k_gemm1(const float* __restrict__ X,
                                                  const float* __restrict__ W,
                                                  const float* __restrict__ As1,
                                                  const float* __restrict__ Ad1, int M) {
    const int BM = 128;
    __shared__ __half As[2][BM][40];
    __shared__ __half Bs[2][32][136];
    __shared__ float  sA[128][4];
    __shared__ float  sD[128][4];
    int t    = threadIdx.x;
    int wid  = t >> 5, lane = t & 31;
    int lr   = lane & 7, lg = lane >> 3;
    int wm   = (wid >> 1) * 32;
    int wn   = (wid & 1) * 64;
    int rowBase = blockIdx.x * BM;
    int colBase = blockIdx.y * BM;
    int hb      = blockIdx.y * 4;

    #pragma unroll
    for (int i = t; i < 512; i += 256) {
        ((float*)sA)[i] = 0.f;
        ((float*)sD)[i] = 0.f;
    }

    float c[2][8][4];
    #pragma unroll
    for (int i = 0; i < 2; i++)
        #pragma unroll
        for (int j = 0; j < 8; j++)
            #pragma unroll
            for (int k = 0; k < 4; k++) c[i][j][k] = 0.f;

    // per-thread load coordinates
    int ar[4], ak[4], br[4], bc[4];
    #pragma unroll
    for (int i = 0; i < 4; i++) {
        int q = t + i * 256;
        ar[i] = q >> 3; ak[i] = (q & 7) * 4;
        br[i] = q >> 5; bc[i] = (q & 31) * 4;
    }

    float4 ra[4], rb[4];
    #pragma unroll
    for (int i = 0; i < 4; i++) {
        int grow = rowBase + ar[i];
        ra[i] = (grow < M) ? *(const float4*)(X + (size_t)grow * 256 + ak[i])
                           : make_float4(0.f, 0.f, 0.f, 0.f);
        rb[i] = *(const float4*)(W + (size_t)br[i] * 256 + colBase + bc[i]);
    }
    #pragma unroll
    for (int i = 0; i < 4; i++) {
        *(__half2*)&As[0][ar[i]][ak[i]]     = __floats2half2_rn(ra[i].x, ra[i].y);
        *(__half2*)&As[0][ar[i]][ak[i] + 2] = __floats2half2_rn(ra[i].z, ra[i].w);
        *(__half2*)&Bs[0][br[i]][bc[i]]     = __floats2half2_rn(rb[i].x, rb[i].y);
        *(__half2*)&Bs[0][br[i]][bc[i] + 2] = __floats2half2_rn(rb[i].z, rb[i].w);
    }
    __syncthreads();

    int cur = 0;
    for (int kt = 0; kt < 256; kt += 32) {
        bool more = (kt + 32) < 256;
        if (more) {
            #pragma unroll
            for (int i = 0; i < 4; i++) {
                int grow = rowBase + ar[i];
                ra[i] = (grow < M) ? *(const float4*)(X + (size_t)grow * 256 + kt + 32 + ak[i])
                                   : make_float4(0.f, 0.f, 0.f, 0.f);
                rb[i] = *(const float4*)(W + (size_t)(kt + 32 + br[i]) * 256 + colBase + bc[i]);
            }
        }
        #pragma unroll
        for (int ks = 0; ks < 2; ks++) {
            uint32_t a[2][4], b[4][4];
            #pragma unroll
            for (int mt = 0; mt < 2; mt++) {
                int row = wm + mt * 16 + lr + (lg & 1) * 8;
                int col = ks * 16 + (lg >> 1) * 8;
                ldsm4(a[mt], sptr(&As[cur][row][col]));
            }
            #pragma unroll
            for (int ng = 0; ng < 4; ng++) {
                int krow = ks * 16 + lr + (lg & 1) * 8;
                int col  = wn + ng * 16 + (lg >> 1) * 8;
                ldsm4t(b[ng], sptr(&Bs[cur][krow][col]));
            }
            #pragma unroll
            for (int mt = 0; mt < 2; mt++)
                #pragma unroll
                for (int nt = 0; nt < 8; nt++)
                    mma16816(c[mt][nt], a[mt], b[nt >> 1][(nt & 1) * 2],
                             b[nt >> 1][(nt & 1) * 2 + 1]);
        }
        if (more) {
            int nxt = cur ^ 1;
            #pragma unroll
            for (int i = 0; i < 4; i++) {
                *(__half2*)&As[nxt][ar[i]][ak[i]]     = __floats2half2_rn(ra[i].x, ra[i].y);
                *(__half2*)&As[nxt][ar[i]][ak[i] + 2] = __floats2half2_rn(ra[i].z, ra[i].w);
                *(__half2*)&Bs[nxt][br[i]][bc[i]]     = __floats2half2_rn(rb[i].x, rb[i].y);
                *(__half2*)&Bs[nxt][br[i]][bc[i] + 2] = __floats2half2_rn(rb[i].z, rb[i].w);
            }
            __syncthreads();
            cur = nxt;
        }
    }

    // epilogue 1: store xp fp16
    #pragma unroll
    for (int mt = 0; mt < 2; mt++) {
        int r0 = rowBase + wm + mt * 16 + (lane >> 2);
        #pragma unroll
        for (int nt = 0; nt < 8; nt++) {
            int col = colBase + wn + nt * 8 + (lane & 3) * 2;
            if (r0 < M)
                *(__half2*)(g_xph + (size_t)r0 * 256 + col) =
                    __floats2half2_rn(c[mt][nt][0], c[mt][nt][1]);
            if (r0 + 8 < M)
                *(__half2*)(g_xph + (size_t)(r0 + 8) * 256 + col) =
                    __floats2half2_rn(c[mt][nt][2], c[mt][nt][3]);
        }
    }

    // epilogue 2: attention logit partials
    float asw[16], adw[16];
    #pragma unroll
    for (int nt = 0; nt < 8; nt++)
        #pragma unroll
        for (int b = 0; b < 2; b++) {
            int col = wn + nt * 8 + (lane & 3) * 2 + b;
            asw[nt * 2 + b] = As1[colBase + col];
            adw[nt * 2 + b] = Ad1[colBase + col];
        }
    int h0 = wn >> 5, h1 = h0 + 1;
    #pragma unroll
    for (int mt = 0; mt < 2; mt++)
        #pragma unroll
        for (int hf = 0; hf < 2; hf++) {
            int rl = wm + mt * 16 + (lane >> 2) + 8 * hf;
            float s0 = 0.f, s1 = 0.f, d0 = 0.f, d1 = 0.f;
            #pragma unroll
            for (int nt = 0; nt < 8; nt++) {
                float v0 = c[mt][nt][hf * 2 + 0];
                float v1 = c[mt][nt][hf * 2 + 1];
                float cs = v0 * asw[nt * 2] + v1 * asw[nt * 2 + 1];
                float cd = v0 * adw[nt * 2] + v1 * adw[nt * 2 + 1];
                if (nt < 4) { s0 += cs; d0 += cd; }
                else        { s1 += cs; d1 += cd; }
            }
            atomicAdd(&sA[rl][h0], s0);
            atomicAdd(&sA[rl][h1], s1);
            atomicAdd(&sD[rl][h0], d0);
            atomicAdd(&sD[rl][h1], d1);
        }
    __syncthreads();
    #pragma unroll
    for (int i = t; i < 512; i += 256) {
        int r = i >> 2, hl = i & 3;
        int grow = rowBase + r;
        if (grow < M) {
            g_asrc[grow * 8 + hb + hl] = sA[r][hl];
            g_adst[grow * 8 + hb + hl] = sD[r][hl];
        }
    }
}

// ---------------- CSR build ----------------
__global__ void k_hist(const void* __restrict__ ei, int e) {
    int t = blockIdx.x * blockDim.x + threadIdx.x;
    int is64 = g_is64;
    int base = 2 * t;
    if (base + 1 < e) {
        int d0, d1;
        if (is64) {
            longlong2 v = ((const longlong2*)ei)[(e >> 1) + t];
            d0 = (int)v.x; d1 = (int)v.y;
        } else {
            int2 v = ((const int2*)ei)[(e >> 1) + t];
            d0 = v.x; d1 = v.y;
        }
        atomicAdd(&g_deg[d0], 1);
        atomicAdd(&g_deg[d1], 1);
    } else if (base < e) {
        int d = load_idx(ei, e + base, is64);
        atomicAdd(&g_deg[d], 1);
    }
}

__global__ void k_scanA(int n) {
    int i = blockIdx.x * 256 + threadIdx.x;
    int lane = threadIdx.x & 31, wid = threadIdx.x >> 5;
    int v = (i < n) ? (g_deg[i] + 1) : 0;
    int x = v;
    #pragma unroll
    for (int o = 1; o < 32; o <<= 1) {
        int y = __shfl_up_sync(0xffffffffu, x, o);
        if (lane >= o) x += y;
    }
    __shared__ int ws[8];
    if (lane == 31) ws[wid] = x;
    __syncthreads();
    if (threadIdx.x < 8) {
        int w = ws[threadIdx.x];
        #pragma unroll
        for (int o = 1; o < 8; o <<= 1) {
            int y = __shfl_up_sync(0xffu, w, o);
            if ((int)threadIdx.x >= o) w += y;
        }
        ws[threadIdx.x] = w;
    }
    __syncthreads();
    int base = (wid ? ws[wid - 1] : 0);
    if (i < n) g_rowstart[i] = base + x - v;
    if (threadIdx.x == 255) g_bsum[blockIdx.x] = ws[7];
}

__global__ void k_scanB(int nb) {
    int t = threadIdx.x;
    int lane = t & 31, wid = t >> 5;
    int v = (t < nb) ? g_bsum[t] : 0;
    int x = v;
    #pragma unroll
    for (int o = 1; o < 32; o <<= 1) {
        int y = __shfl_up_sync(0xffffffffu, x, o);
        if (lane >= o) x += y;
    }
    __shared__ int ws[8];
    if (lane == 31) ws[wid] = x;
    __syncthreads();
    if (t < 8) {
        int w = ws[t];
        #pragma unroll
        for (int o = 1; o < 8; o <<= 1) {
            int y = __shfl_up_sync(0xffu, w, o);
            if (t >= o) w += y;
        }
        ws[t] = w;
    }
    __syncthreads();
    int base = (wid ? ws[wid - 1] : 0);
    g_boff[t] = base + x - v;
}

__global__ void k_scanC(int n, int total) {
    int i = blockIdx.x * 256 + threadIdx.x;
    if (i < n) g_rowstart[i] += g_boff[i >> 8];
    if (i == 0) g_rowstart[n] = total;
}

__global__ void k_scatter(const void* __restrict__ ei, int e, int n) {
    int t = blockIdx.x * blockDim.x + threadIdx.x;
    int ep = e >> 1;
    int is64 = g_is64;
    if (t < ep) {
        int s0, s1, d0, d1;
        if (is64) {
            longlong2 vs = ((const longlong2*)ei)[t];
            longlong2 vd = ((const longlong2*)ei)[ep + t];
            s0 = (int)vs.x; s1 = (int)vs.y; d0 = (int)vd.x; d1 = (int)vd.y;
        } else {
            int2 vs = ((const int2*)ei)[t];
            int2 vd = ((const int2*)ei)[ep + t];
            s0 = vs.x; s1 = vs.y; d0 = vd.x; d1 = vd.y;
        }
        int p0 = atomicAdd(&g_cursor[d0], 1);
        g_csr[g_rowstart[d0] + p0] = s0;
        int p1 = atomicAdd(&g_cursor[d1], 1);
        g_csr[g_rowstart[d1] + p1] = s1;
    } else if ((e & 1) && t == ep) {
        int src = load_idx(ei, e - 1, is64);
        int dst = load_idx(ei, 2 * e - 1, is64);
        int p = atomicAdd(&g_cursor[dst], 1);
        g_csr[g_rowstart[dst] + p] = src;
    } else {
        int node = t - ep - (e & 1);
        if (node < n) {
            int p = atomicAdd(&g_cursor[node], 1);
            g_csr[g_rowstart[node] + p] = node;
        }
    }
}

// ---------------- layer-1 aggregation + fused layer-2 projection ----------------
// Lane l owns channels [8l, 8l+8) -> all within head (l>>2). One LDG.128/lane/row.
__global__ void k_agg1(const float* __restrict__ b1, const float* __restrict__ W2,
                       const float* __restrict__ as2w, const float* __restrict__ ad2w, int n) {
    int w    = (blockIdx.x * blockDim.x + threadIdx.x) >> 5;
    int lane = threadIdx.x & 31;
    if (w >= n) return;
    int row = g_rowstart[w], end = g_rowstart[w + 1];
    float adl = (lane < 8) ? g_adst[w * 8 + lane] : 0.f;
    int hsel = lane >> 2;     // head whose p this lane needs

    float s = 0.f;
    float2 acc[4] = {{0.f,0.f},{0.f,0.f},{0.f,0.f},{0.f,0.f}};

    int j = row;
    for (; j + 1 < end; j += 2) {
        int sa = g_csr[j], sb = g_csr[j + 1];
        float4 va = *(const float4*)(g_xph + (size_t)sa * 256 + lane * 8);
        float4 vb = *(const float4*)(g_xph + (size_t)sb * 256 + lane * 8);
        float pa = 0.f, pb = 0.f;
        if (lane < 8) {
            float ea = g_asrc[sa * 8 + lane] + adl;
            float eb = g_asrc[sb * 8 + lane] + adl;
            ea = fmaxf(ea, 0.2f * ea);
            eb = fmaxf(eb, 0.2f * eb);
            pa = __expf(ea);
            pb = __expf(eb);
            s += pa + pb;
        }
        float pha = __shfl_sync(0xffffffffu, pa, hsel);
        float phb = __shfl_sync(0xffffffffu, pb, hsel);
        const __half2* ha = (const __half2*)&va;
        const __half2* hbp = (const __half2*)&vb;
        #pragma unroll
        for (int k = 0; k < 4; k++) {
            float2 fa = __half22float2(ha[k]);
            float2 fb = __half22float2(hbp[k]);
            acc[k].x = fmaf(fa.x, pha, fmaf(fb.x, phb, acc[k].x));
            acc[k].y = fmaf(fa.y, pha, fmaf(fb.y, phb, acc[k].y));
        }
    }
    if (j < end) {
        int sa = g_csr[j];
        float4 va = *(const float4*)(g_xph + (size_t)sa * 256 + lane * 8);
        float pa = 0.f;
        if (lane < 8) {
            float ea = g_asrc[sa * 8 + lane] + adl;
            ea = fmaxf(ea, 0.2f * ea);
            pa = __expf(ea);
            s += pa;
        }
        float pha = __shfl_sync(0xffffffffu, pa, hsel);
        const __half2* ha = (const __half2*)&va;
        #pragma unroll
        for (int k = 0; k < 4; k++) {
            float2 fa = __half22float2(ha[k]);
            acc[k].x = fmaf(fa.x, pha, acc[k].x);
            acc[k].y = fmaf(fa.y, pha, acc[k].y);
        }
    }

    // epilogue: h = relu(acc/s + b1); project to (o0,o1) via W2 rows [8l,8l+8)
    float sh = __shfl_sync(0xffffffffu, s, hsel);
    float inv = 1.f / sh;
    float4 b4a = *(const float4*)(b1 + 8 * lane);
    float4 b4b = *(const float4*)(b1 + 8 * lane + 4);
    float hch[8];
    hch[0] = fmaxf(acc[0].x * inv + b4a.x, 0.f);
    hch[1] = fmaxf(acc[0].y * inv + b4a.y, 0.f);
    hch[2] = fmaxf(acc[1].x * inv + b4a.z, 0.f);
    hch[3] = fmaxf(acc[1].y * inv + b4a.w, 0.f);
    hch[4] = fmaxf(acc[2].x * inv + b4b.x, 0.f);
    hch[5] = fmaxf(acc[2].y * inv + b4b.y, 0.f);
    hch[6] = fmaxf(acc[3].x * inv + b4b.z, 0.f);
    hch[7] = fmaxf(acc[3].y * inv + b4b.w, 0.f);
    float o0 = 0.f, o1 = 0.f;
    #pragma unroll
    for (int q = 0; q < 4; q++) {
        float4 w4 = *(const float4*)(W2 + 16 * lane + 4 * q);
        o0 += hch[2 * q] * w4.x + hch[2 * q + 1] * w4.z;
        o1 += hch[2 * q] * w4.y + hch[2 * q + 1] * w4.w;
    }
    #pragma unroll
    for (int off = 16; off; off >>= 1) {
        o0 += __shfl_xor_sync(0xffffffffu, o0, off);
        o1 += __shfl_xor_sync(0xffffffffu, o1, off);
    }
    if (lane == 0) {
        g_hp[w * 2 + 0] = o0;
        g_hp[w * 2 + 1] = o1;
        g_as2[w] = o0 * as2w[0] + o1 * as2w[1];
        g_ad2[w] = o0 * ad2w[0] + o1 * ad2w[1];
    }
}

// ---------------- layer-2 aggregation ----------------
__global__ void k_agg2(const float* __restrict__ b2, float* __restrict__ out, int n) {
    int w    = (blockIdx.x * blockDim.x + threadIdx.x) >> 5;
    int lane = threadIdx.x & 31;
    if (w >= n) return;
    int row = g_rowstart[w], end = g_rowstart[w + 1];
    float adn = g_ad2[w];

    float s = 0.f, a0 = 0.f, a1 = 0.f;
    for (int j = row + lane; j < end; j += 32) {
        int src = g_csr[j];
        float e = g_as2[src] + adn;
        e = fmaxf(e, 0.2f * e);
        float p = __expf(e);
        float2 hp = *(const float2*)(g_hp + 2 * src);
        s  += p;
        a0 = fmaf(hp.x, p, a0);
        a1 = fmaf(hp.y, p, a1);
    }
    #pragma unroll
    for (int off = 16; off; off >>= 1) {
        s  += __shfl_xor_sync(0xffffffffu, s,  off);
        a0 += __shfl_xor_sync(0xffffffffu, a0, off);
        a1 += __shfl_xor_sync(0xffffffffu, a1, off);
    }
    if (lane == 0) {
        out[w * 2 + 0] = a0 / s + b2[0];
        out[w * 2 + 1] = a1 / s + b2[1];
    }
}

// ---------------- launch ----------------
extern "C" void kernel_launch(void* const* d_in, const int* in_sizes, int n_in,
                              void* d_out, int out_size) {
    const float* x   = (const float*)d_in[0];
    const void*  ei  = d_in[1];
    const float* W1  = (const float*)d_in[2];
    const float* as1 = (const float*)d_in[3];
    const float* ad1 = (const float*)d_in[4];
    const float* b1  = (const float*)d_in[5];
    const float* W2  = (const float*)d_in[6];
    const float* as2 = (const float*)d_in[7];
    const float* ad2 = (const float*)d_in[8];
    const float* b2  = (const float*)d_in[9];

    int n = in_sizes[0] / 256;
    int e = in_sizes[1] / 2;

    int warpBlocks = (n * 32 + 255) / 256;
    int nb = (n + 255) / 256;

    static cudaStream_t s1 = 0, s2 = 0;
    static cudaEvent_t ev0 = 0, ev1 = 0, ev2 = 0;
    if (!s1) {
        cudaStreamCreateWithFlags(&s1, cudaStreamNonBlocking);
        cudaStreamCreateWithFlags(&s2, cudaStreamNonBlocking);
        cudaEventCreateWithFlags(&ev0, cudaEventDisableTiming);
        cudaEventCreateWithFlags(&ev1, cudaEventDisableTiming);
        cudaEventCreateWithFlags(&ev2, cudaEventDisableTiming);
    }

    cudaEventRecord(ev0, 0);
    cudaStreamWaitEvent(s1, ev0, 0);
    cudaStreamWaitEvent(s2, ev0, 0);

    dim3 gg((n + 127) / 128, 2);
    k_gemm1<<<gg, 256, 0, s1>>>(x, W1, as1, ad1, n);

    k_init<<<(n + 255) / 256, 256, 0, s2>>>((const int*)ei, n);
    k_hist<<<((e >> 1) + 256) / 256, 256, 0, s2>>>(ei, e);
    k_scanA<<<nb, 256, 0, s2>>>(n);
    k_scanB<<<1, 256, 0, s2>>>(nb);
    k_scanC<<<nb, 256, 0, s2>>>(n, e + n);
    int scatterThreads = (e >> 1) + (e & 1) + n;
    k_scatter<<<(scatterThreads + 255) / 256, 256, 0, s2>>>(ei, e, n);

    cudaEventRecord(ev1, s1);
    cudaEventRecord(ev2, s2);
    cudaStreamWaitEvent(0, ev1, 0);
    cudaStreamWaitEvent(0, ev2, 0);

    k_agg1<<<warpBlocks, 256>>>(b1, W2, as2, ad2, n);
    k_agg2<<<warpBlocks, 256>>>(b2, (float*)d_out, n);
}

// round 7
// speedup vs baseline: 2.9489x; 1.0078x over previous
#include <cuda_runtime.h>
#include <cuda_fp16.h>
#include <math.h>
#include <stdint.h>

#define NMAX 50000
#define EMAX 800000
#define TOT_E (EMAX + NMAX)

// ---------------- scratch ----------------
__device__ __half g_xph[NMAX * 256];
__device__ float  g_asrc[NMAX * 8];
__device__ float  g_adst[NMAX * 8];
__device__ int    g_deg[NMAX];
__device__ int    g_rowstart[NMAX + 1];
__device__ int    g_cursor[NMAX];
__device__ int    g_csr[TOT_E];
__device__ float  g_hp[NMAX * 2];
__device__ float  g_as2[NMAX];
__device__ float  g_ad2[NMAX];
__device__ int    g_is64;
__device__ int    g_bsum[256];
__device__ int    g_boff[256];
__device__ int    g_scancnt;
__device__ int    g_scanflag;

// ---------------- mma helpers ----------------
__device__ __forceinline__ uint32_t sptr(const void* p) {
    return (uint32_t)__cvta_generic_to_shared(p);
}
__device__ __forceinline__ void ldsm4(uint32_t* r, uint32_t a) {
    asm volatile("ldmatrix.sync.aligned.m8n8.x4.shared.b16 {%0,%1,%2,%3},[%4];"
        : "=r"(r[0]), "=r"(r[1]), "=r"(r[2]), "=r"(r[3]) : "r"(a));
}
__device__ __forceinline__ void ldsm4t(uint32_t* r, uint32_t a) {
    asm volatile("ldmatrix.sync.aligned.m8n8.x4.trans.shared.b16 {%0,%1,%2,%3},[%4];"
        : "=r"(r[0]), "=r"(r[1]), "=r"(r[2]), "=r"(r[3]) : "r"(a));
}
__device__ __forceinline__ void mma16816(float* c, const uint32_t* a, uint32_t b0, uint32_t b1) {
    asm volatile(
        "mma.sync.aligned.m16n8k16.row.col.f32.f16.f16.f32 "
        "{%0,%1,%2,%3},{%4,%5,%6,%7},{%8,%9},{%0,%1,%2,%3};"
        : "+f"(c[0]), "+f"(c[1]), "+f"(c[2]), "+f"(c[3])
        : "r"(a[0]), "r"(a[1]), "r"(a[2]), "r"(a[3]), "r"(b0), "r"(b1));
}

__device__ __forceinline__ int load_idx(const void* ei, int i, int is64) {
    if (is64) return (int)((const long long*)ei)[i];
    return ((const int*)ei)[i];
}

// ---------------- init: zero counters, reset scan state, dtype detect ----------------
__global__ void k_init(const int* __restrict__ ei32, int n) {
    int t = blockIdx.x * blockDim.x + threadIdx.x;
    if (t < n) { g_deg[t] = 0; g_cursor[t] = 0; }
    if (blockIdx.x == 0 && threadIdx.x < 32) {
        int bad = 0;
        #pragma unroll
        for (int i = threadIdx.x; i < 64; i += 32)
            bad |= (ei32[2 * i + 1] != 0);
        unsigned m = __ballot_sync(0xffffffffu, bad);
        if (threadIdx.x == 0) {
            g_is64 = (m == 0);
            g_scancnt = 0;
            g_scanflag = 0;
        }
    }
}

// ---------------- layer-1 GEMM + fused attention logits (double-buffered) ----------------
__global__ void __launch_bounds__(256, 2) k_gemm1(const float* __restrict__ X,
                                                  const float* __restrict__ W,
                                                  const float* __restrict__ As1,
                                                  const float* __restrict__ Ad1, int M) {
    const int BM = 128;
    __shared__ __half As[2][BM][40];
    __shared__ __half Bs[2][32][136];
    __shared__ float  sA[128][4];
    __shared__ float  sD[128][4];
    int t    = threadIdx.x;
    int wid  = t >> 5, lane = t & 31;
    int lr   = lane & 7, lg = lane >> 3;
    int wm   = (wid >> 1) * 32;
    int wn   = (wid & 1) * 64;
    int rowBase = blockIdx.x * BM;
    int colBase = blockIdx.y * BM;
    int hb      = blockIdx.y * 4;

    #pragma unroll
    for (int i = t; i < 512; i += 256) {
        ((float*)sA)[i] = 0.f;
        ((float*)sD)[i] = 0.f;
    }

    float c[2][8][4];
    #pragma unroll
    for (int i = 0; i < 2; i++)
        #pragma unroll
        for (int j = 0; j < 8; j++)
            #pragma unroll
            for (int k = 0; k < 4; k++) c[i][j][k] = 0.f;

    int ar[4], ak[4], br[4], bc[4];
    #pragma unroll
    for (int i = 0; i < 4; i++) {
        int q = t + i * 256;
        ar[i] = q >> 3; ak[i] = (q & 7) * 4;
        br[i] = q >> 5; bc[i] = (q & 31) * 4;
    }

    float4 ra[4], rb[4];
    #pragma unroll
    for (int i = 0; i < 4; i++) {
        int grow = rowBase + ar[i];
        ra[i] = (grow < M) ? *(const float4*)(X + (size_t)grow * 256 + ak[i])
                           : make_float4(0.f, 0.f, 0.f, 0.f);
        rb[i] = *(const float4*)(W + (size_t)br[i] * 256 + colBase + bc[i]);
    }
    #pragma unroll
    for (int i = 0; i < 4; i++) {
        *(__half2*)&As[0][ar[i]][ak[i]]     = __floats2half2_rn(ra[i].x, ra[i].y);
        *(__half2*)&As[0][ar[i]][ak[i] + 2] = __floats2half2_rn(ra[i].z, ra[i].w);
        *(__half2*)&Bs[0][br[i]][bc[i]]     = __floats2half2_rn(rb[i].x, rb[i].y);
        *(__half2*)&Bs[0][br[i]][bc[i] + 2] = __floats2half2_rn(rb[i].z, rb[i].w);
    }
    __syncthreads();

    int cur = 0;
    for (int kt = 0; kt < 256; kt += 32) {
        bool more = (kt + 32) < 256;
        if (more) {
            #pragma unroll
            for (int i = 0; i < 4; i++) {
                int grow = rowBase + ar[i];
                ra[i] = (grow < M) ? *(const float4*)(X + (size_t)grow * 256 + kt + 32 + ak[i])
                                   : make_float4(0.f, 0.f, 0.f, 0.f);
                rb[i] = *(const float4*)(W + (size_t)(kt + 32 + br[i]) * 256 + colBase + bc[i]);
            }
        }
        #pragma unroll
        for (int ks = 0; ks < 2; ks++) {
            uint32_t a[2][4], b[4][4];
            #pragma unroll
            for (int mt = 0; mt < 2; mt++) {
                int row = wm + mt * 16 + lr + (lg & 1) * 8;
                int col = ks * 16 + (lg >> 1) * 8;
                ldsm4(a[mt], sptr(&As[cur][row][col]));
            }
            #pragma unroll
            for (int ng = 0; ng < 4; ng++) {
                int krow = ks * 16 + lr + (lg & 1) * 8;
                int col  = wn + ng * 16 + (lg >> 1) * 8;
                ldsm4t(b[ng], sptr(&Bs[cur][krow][col]));
            }
            #pragma unroll
            for (int mt = 0; mt < 2; mt++)
                #pragma unroll
                for (int nt = 0; nt < 8; nt++)
                    mma16816(c[mt][nt], a[mt], b[nt >> 1][(nt & 1) * 2],
                             b[nt >> 1][(nt & 1) * 2 + 1]);
        }
        if (more) {
            int nxt = cur ^ 1;
            #pragma unroll
            for (int i = 0; i < 4; i++) {
                *(__half2*)&As[nxt][ar[i]][ak[i]]     = __floats2half2_rn(ra[i].x, ra[i].y);
                *(__half2*)&As[nxt][ar[i]][ak[i] + 2] = __floats2half2_rn(ra[i].z, ra[i].w);
                *(__half2*)&Bs[nxt][br[i]][bc[i]]     = __floats2half2_rn(rb[i].x, rb[i].y);
                *(__half2*)&Bs[nxt][br[i]][bc[i] + 2] = __floats2half2_rn(rb[i].z, rb[i].w);
            }
            __syncthreads();
            cur = nxt;
        }
    }

    // epilogue 1: store xp fp16
    #pragma unroll
    for (int mt = 0; mt < 2; mt++) {
        int r0 = rowBase + wm + mt * 16 + (lane >> 2);
        #pragma unroll
        for (int nt = 0; nt < 8; nt++) {
            int col = colBase + wn + nt * 8 + (lane & 3) * 2;
            if (r0 < M)
                *(__half2*)(g_xph + (size_t)r0 * 256 + col) =
                    __floats2half2_rn(c[mt][nt][0], c[mt][nt][1]);
            if (r0 + 8 < M)
                *(__half2*)(g_xph + (size_t)(r0 + 8) * 256 + col) =
                    __floats2half2_rn(c[mt][nt][2], c[mt][nt][3]);
        }
    }

    // epilogue 2: attention logit partials
    float asw[16], adw[16];
    #pragma unroll
    for (int nt = 0; nt < 8; nt++)
        #pragma unroll
        for (int b = 0; b < 2; b++) {
            int col = wn + nt * 8 + (lane & 3) * 2 + b;
            asw[nt * 2 + b] = As1[colBase + col];
            adw[nt * 2 + b] = Ad1[colBase + col];
        }
    int h0 = wn >> 5, h1 = h0 + 1;
    #pragma unroll
    for (int mt = 0; mt < 2; mt++)
        #pragma unroll
        for (int hf = 0; hf < 2; hf++) {
            int rl = wm + mt * 16 + (lane >> 2) + 8 * hf;
            float s0 = 0.f, s1 = 0.f, d0 = 0.f, d1 = 0.f;
            #pragma unroll
            for (int nt = 0; nt < 8; nt++) {
                float v0 = c[mt][nt][hf * 2 + 0];
                float v1 = c[mt][nt][hf * 2 + 1];
                float cs = v0 * asw[nt * 2] + v1 * asw[nt * 2 + 1];
                float cd = v0 * adw[nt * 2] + v1 * adw[nt * 2 + 1];
                if (nt < 4) { s0 += cs; d0 += cd; }
                else        { s1 += cs; d1 += cd; }
            }
            atomicAdd(&sA[rl][h0], s0);
            atomicAdd(&sA[rl][h1], s1);
            atomicAdd(&sD[rl][h0], d0);
            atomicAdd(&sD[rl][h1], d1);
        }
    __syncthreads();
    #pragma unroll
    for (int i = t; i < 512; i += 256) {
        int r = i >> 2, hl = i & 3;
        int grow = rowBase + r;
        if (grow < M) {
            g_asrc[grow * 8 + hb + hl] = sA[r][hl];
            g_adst[grow * 8 + hb + hl] = sD[r][hl];
        }
    }
}

// ---------------- CSR build ----------------
__global__ void k_hist(const void* __restrict__ ei, int e) {
    int t = blockIdx.x * blockDim.x + threadIdx.x;
    int is64 = g_is64;
    int base = 2 * t;
    if (base + 1 < e) {
        int d0, d1;
        if (is64) {
            longlong2 v = ((const longlong2*)ei)[(e >> 1) + t];
            d0 = (int)v.x; d1 = (int)v.y;
        } else {
            int2 v = ((const int2*)ei)[(e >> 1) + t];
            d0 = v.x; d1 = v.y;
        }
        atomicAdd(&g_deg[d0], 1);
        atomicAdd(&g_deg[d1], 1);
    } else if (base < e) {
        int d = load_idx(ei, e + base, is64);
        atomicAdd(&g_deg[d], 1);
    }
}

// ---------------- single-pass fused scan (block scan + last-block middle scan) --------
__global__ void k_scanF(int n, int total) {
    int b = blockIdx.x;
    int i = b * 256 + threadIdx.x;
    int lane = threadIdx.x & 31, wid = threadIdx.x >> 5;
    int v = (i < n) ? (g_deg[i] + 1) : 0;
    int x = v;
    #pragma unroll
    for (int o = 1; o < 32; o <<= 1) {
        int y = __shfl_up_sync(0xffffffffu, x, o);
        if (lane >= o) x += y;
    }
    __shared__ int ws[8];
    __shared__ int isLast;
    if (lane == 31) ws[wid] = x;
    __syncthreads();
    if (threadIdx.x < 8) {
        int w = ws[threadIdx.x];
        #pragma unroll
        for (int o = 1; o < 8; o <<= 1) {
            int y = __shfl_up_sync(0xffu, w, o);
            if ((int)threadIdx.x >= o) w += y;
        }
        ws[threadIdx.x] = w;
    }
    __syncthreads();
    int base = (wid ? ws[wid - 1] : 0);
    int loc = base + x - v;                    // block-local exclusive
    if (threadIdx.x == 0) g_bsum[b] = ws[7];
    __threadfence();
    if (threadIdx.x == 0) {
        int old = atomicAdd(&g_scancnt, 1);
        isLast = (old == (int)gridDim.x - 1);
    }
    __syncthreads();
    if (isLast) {
        // scan the block sums (<=256 of them) with this block
        int t2 = threadIdx.x;
        int vv = (t2 < (int)gridDim.x) ? g_bsum[t2] : 0;
        int xx = vv;
        #pragma unroll
        for (int o = 1; o < 32; o <<= 1) {
            int y = __shfl_up_sync(0xffffffffu, xx, o);
            if (lane >= o) xx += y;
        }
        __shared__ int ws2[8];
        if (lane == 31) ws2[wid] = xx;
        __syncthreads();
        if (t2 < 8) {
            int w = ws2[t2];
            #pragma unroll
            for (int o = 1; o < 8; o <<= 1) {
                int y = __shfl_up_sync(0xffu, w, o);
                if (t2 >= o) w += y;
            }
            ws2[t2] = w;
        }
        __syncthreads();
        int b2 = (wid ? ws2[wid - 1] : 0);
        g_boff[t2] = b2 + xx - vv;
        __threadfence();
        __syncthreads();
        if (threadIdx.x == 0) atomicExch(&g_scanflag, 1);
    } else if (threadIdx.x == 0) {
        while (atomicAdd(&g_scanflag, 0) == 0) __nanosleep(64);
    }
    __syncthreads();
    int boff = *(volatile int*)&g_boff[b];
    if (i < n) g_rowstart[i] = loc + boff;
    if (i == 0) g_rowstart[n] = total;
}

__global__ void k_scatter(const void* __restrict__ ei, int e, int n) {
    int t = blockIdx.x * blockDim.x + threadIdx.x;
    int ep = e >> 1;
    int is64 = g_is64;
    if (t < ep) {
        int s0, s1, d0, d1;
        if (is64) {
            longlong2 vs = ((const longlong2*)ei)[t];
            longlong2 vd = ((const longlong2*)ei)[ep + t];
            s0 = (int)vs.x; s1 = (int)vs.y; d0 = (int)vd.x; d1 = (int)vd.y;
        } else {
            int2 vs = ((const int2*)ei)[t];
            int2 vd = ((const int2*)ei)[ep + t];
            s0 = vs.x; s1 = vs.y; d0 = vd.x; d1 = vd.y;
        }
        int p0 = atomicAdd(&g_cursor[d0], 1);
        g_csr[g_rowstart[d0] + p0] = s0;
        int p1 = atomicAdd(&g_cursor[d1], 1);
        g_csr[g_rowstart[d1] + p1] = s1;
    } else if ((e & 1) && t == ep) {
        int src = load_idx(ei, e - 1, is64);
        int dst = load_idx(ei, 2 * e - 1, is64);
        int p = atomicAdd(&g_cursor[dst], 1);
        g_csr[g_rowstart[dst] + p] = src;
    } else {
        int node = t - ep - (e & 1);
        if (node < n) {
            int p = atomicAdd(&g_cursor[node], 1);
            g_csr[g_rowstart[node] + p] = node;
        }
    }
}

// ---------------- layer-1 aggregation + fused layer-2 projection (unroll 4) ----------
__global__ void k_agg1(const float* __restrict__ b1, const float* __restrict__ W2,
                       const float* __restrict__ as2w, const float* __restrict__ ad2w, int n) {
    int w    = (blockIdx.x * blockDim.x + threadIdx.x) >> 5;
    int lane = threadIdx.x & 31;
    if (w >= n) return;
    int row = g_rowstart[w], end = g_rowstart[w + 1];
    float adl = (lane < 8) ? g_adst[w * 8 + lane] : 0.f;
    int hsel = lane >> 2;

    float s = 0.f;
    float2 acc[4] = {{0.f,0.f},{0.f,0.f},{0.f,0.f},{0.f,0.f}};

    int j = row;
    for (; j + 3 < end; j += 4) {
        int n0 = g_csr[j], n1 = g_csr[j + 1], n2 = g_csr[j + 2], n3 = g_csr[j + 3];
        float4 v0 = *(const float4*)(g_xph + (size_t)n0 * 256 + lane * 8);
        float4 v1 = *(const float4*)(g_xph + (size_t)n1 * 256 + lane * 8);
        float4 v2 = *(const float4*)(g_xph + (size_t)n2 * 256 + lane * 8);
        float4 v3 = *(const float4*)(g_xph + (size_t)n3 * 256 + lane * 8);
        float p0 = 0.f, p1 = 0.f, p2 = 0.f, p3 = 0.f;
        if (lane < 8) {
            float e0 = g_asrc[n0 * 8 + lane] + adl;
            float e1 = g_asrc[n1 * 8 + lane] + adl;
            float e2 = g_asrc[n2 * 8 + lane] + adl;
            float e3 = g_asrc[n3 * 8 + lane] + adl;
            e0 = fmaxf(e0, 0.2f * e0); e1 = fmaxf(e1, 0.2f * e1);
            e2 = fmaxf(e2, 0.2f * e2); e3 = fmaxf(e3, 0.2f * e3);
            p0 = __expf(e0); p1 = __expf(e1);
            p2 = __expf(e2); p3 = __expf(e3);
            s += (p0 + p1) + (p2 + p3);
        }
        float q0 = __shfl_sync(0xffffffffu, p0, hsel);
        float q1 = __shfl_sync(0xffffffffu, p1, hsel);
        float q2 = __shfl_sync(0xffffffffu, p2, hsel);
        float q3 = __shfl_sync(0xffffffffu, p3, hsel);
        const __half2* h0 = (const __half2*)&v0;
        const __half2* h1 = (const __half2*)&v1;
        const __half2* h2 = (const __half2*)&v2;
        const __half2* h3 = (const __half2*)&v3;
        #pragma unroll
        for (int k = 0; k < 4; k++) {
            float2 f0 = __half22float2(h0[k]);
            float2 f1 = __half22float2(h1[k]);
            float2 f2 = __half22float2(h2[k]);
            float2 f3 = __half22float2(h3[k]);
            acc[k].x = fmaf(f0.x, q0, fmaf(f1.x, q1, fmaf(f2.x, q2, fmaf(f3.x, q3, acc[k].x))));
            acc[k].y = fmaf(f0.y, q0, fmaf(f1.y, q1, fmaf(f2.y, q2, fmaf(f3.y, q3, acc[k].y))));
        }
    }
    for (; j < end; j++) {
        int n0 = g_csr[j];
        float4 v0 = *(const float4*)(g_xph + (size_t)n0 * 256 + lane * 8);
        float p0 = 0.f;
        if (lane < 8) {
            float e0 = g_asrc[n0 * 8 + lane] + adl;
            e0 = fmaxf(e0, 0.2f * e0);
            p0 = __expf(e0);
            s += p0;
        }
        float q0 = __shfl_sync(0xffffffffu, p0, hsel);
        const __half2* h0 = (const __half2*)&v0;
        #pragma unroll
        for (int k = 0; k < 4; k++) {
            float2 f0 = __half22float2(h0[k]);
            acc[k].x = fmaf(f0.x, q0, acc[k].x);
            acc[k].y = fmaf(f0.y, q0, acc[k].y);
        }
    }

    float sh = __shfl_sync(0xffffffffu, s, hsel);
    float inv = 1.f / sh;
    float4 b4a = *(const float4*)(b1 + 8 * lane);
    float4 b4b = *(const float4*)(b1 + 8 * lane + 4);
    float hch[8];
    hch[0] = fmaxf(acc[0].x * inv + b4a.x, 0.f);
    hch[1] = fmaxf(acc[0].y * inv + b4a.y, 0.f);
    hch[2] = fmaxf(acc[1].x * inv + b4a.z, 0.f);
    hch[3] = fmaxf(acc[1].y * inv + b4a.w, 0.f);
    hch[4] = fmaxf(acc[2].x * inv + b4b.x, 0.f);
    hch[5] = fmaxf(acc[2].y * inv + b4b.y, 0.f);
    hch[6] = fmaxf(acc[3].x * inv + b4b.z, 0.f);
    hch[7] = fmaxf(acc[3].y * inv + b4b.w, 0.f);
    float o0 = 0.f, o1 = 0.f;
    #pragma unroll
    for (int q = 0; q < 4; q++) {
        float4 w4 = *(const float4*)(W2 + 16 * lane + 4 * q);
        o0 += hch[2 * q] * w4.x + hch[2 * q + 1] * w4.z;
        o1 += hch[2 * q] * w4.y + hch[2 * q + 1] * w4.w;
    }
    #pragma unroll
    for (int off = 16; off; off >>= 1) {
        o0 += __shfl_xor_sync(0xffffffffu, o0, off);
        o1 += __shfl_xor_sync(0xffffffffu, o1, off);
    }
    if (lane == 0) {
        g_hp[w * 2 + 0] = o0;
        g_hp[w * 2 + 1] = o1;
        g_as2[w] = o0 * as2w[0] + o1 * as2w[1];
        g_ad2[w] = o0 * ad2w[0] + o1 * ad2w[1];
    }
}

// ---------------- layer-2 aggregation ----------------
__global__ void k_agg2(const float* __restrict__ b2, float* __restrict__ out, int n) {
    int w    = (blockIdx.x * blockDim.x + threadIdx.x) >> 5;
    int lane = threadIdx.x & 31;
    if (w >= n) return;
    int row = g_rowstart[w], end = g_rowstart[w + 1];
    float adn = g_ad2[w];

    float s = 0.f, a0 = 0.f, a1 = 0.f;
    for (int j = row + lane; j < end; j += 32) {
        int src = g_csr[j];
        float e = g_as2[src] + adn;
        e = fmaxf(e, 0.2f * e);
        float p = __expf(e);
        float2 hp = *(const float2*)(g_hp + 2 * src);
        s  += p;
        a0 = fmaf(hp.x, p, a0);
        a1 = fmaf(hp.y, p, a1);
    }
    #pragma unroll
    for (int off = 16; off; off >>= 1) {
        s  += __shfl_xor_sync(0xffffffffu, s,  off);
        a0 += __shfl_xor_sync(0xffffffffu, a0, off);
        a1 += __shfl_xor_sync(0xffffffffu, a1, off);
    }
    if (lane == 0) {
        out[w * 2 + 0] = a0 / s + b2[0];
        out[w * 2 + 1] = a1 / s + b2[1];
    }
}

// ---------------- launch ----------------
extern "C" void kernel_launch(void* const* d_in, const int* in_sizes, int n_in,
                              void* d_out, int out_size) {
    const float* x   = (const float*)d_in[0];
    const void*  ei  = d_in[1];
    const float* W1  = (const float*)d_in[2];
    const float* as1 = (const float*)d_in[3];
    const float* ad1 = (const float*)d_in[4];
    const float* b1  = (const float*)d_in[5];
    const float* W2  = (const float*)d_in[6];
    const float* as2 = (const float*)d_in[7];
    const float* ad2 = (const float*)d_in[8];
    const float* b2  = (const float*)d_in[9];

    int n = in_sizes[0] / 256;
    int e = in_sizes[1] / 2;

    int warpBlocks = (n * 32 + 255) / 256;
    int nb = (n + 255) / 256;   // 196 <= 256 (required by fused scan)

    static cudaStream_t s1 = 0, s2 = 0;
    static cudaEvent_t ev0 = 0, ev1 = 0, ev2 = 0;
    if (!s1) {
        cudaStreamCreateWithFlags(&s1, cudaStreamNonBlocking);
        cudaStreamCreateWithFlags(&s2, cudaStreamNonBlocking);
        cudaEventCreateWithFlags(&ev0, cudaEventDisableTiming);
        cudaEventCreateWithFlags(&ev1, cudaEventDisableTiming);
        cudaEventCreateWithFlags(&ev2, cudaEventDisableTiming);
    }

    cudaEventRecord(ev0, 0);
    cudaStreamWaitEvent(s1, ev0, 0);
    cudaStreamWaitEvent(s2, ev0, 0);

    // branch A: GEMM + fused logits
    dim3 gg((n + 127) / 128, 2);
    k_gemm1<<<gg, 256, 0, s1>>>(x, W1, as1, ad1, n);

    // branch B: CSR build
    k_init<<<(n + 255) / 256, 256, 0, s2>>>((const int*)ei, n);
    k_hist<<<((e >> 1) + 256) / 256, 256, 0, s2>>>(ei, e);
    k_scanF<<<nb, 256, 0, s2>>>(n, e + n);
    int scatterThreads = (e >> 1) + (e & 1) + n;
    k_scatter<<<(scatterThreads + 255) / 256, 256, 0, s2>>>(ei, e, n);

    // join onto s1, then run aggs there (one fewer stream hop)
    cudaEventRecord(ev2, s2);
    cudaStreamWaitEvent(s1, ev2, 0);

    k_agg1<<<warpBlocks, 256, 0, s1>>>(b1, W2, as2, ad2, n);
    k_agg2<<<warpBlocks, 256, 0, s1>>>(b2, (float*)d_out, n);

    // hand result back to the capture (default) stream
    cudaEventRecord(ev1, s1);
    cudaStreamWaitEvent(0, ev1, 0);
}